// round 8
// baseline (speedup 1.0000x reference)
#include <cuda_runtime.h>
#include <cuda_bf16.h>
#include <cstdint>

// Dims fixed: B=4, S=256, D_MODEL=2048, H=256, HEAD_DIM=8; M = B*S = 1024.
#define M_DIM 1024
#define N_DIM 2048
#define K_DIM 2048
#define HEADS 256
#define WSZ   (K_DIM * N_DIM)

// ---------------- scratch ----------------
__device__ float g_q  [M_DIM * N_DIM];
__device__ float g_k  [M_DIM * N_DIM];
__device__ float g_v  [M_DIM * N_DIM];
__device__ float g_att[M_DIM * N_DIM];
__device__ float g_w  [4 * WSZ];        // tf32-pre-rounded weights, original [K][N] layout

// ---------------- helpers ----------------
__device__ __forceinline__ float f2tff(float x) {
    float r;
    asm("cvt.rna.tf32.f32 %0, %1;" : "=f"(r) : "f"(x));
    return r;
}
__device__ __forceinline__ uint32_t smem_u32(const void* p) {
    uint32_t a;
    asm("{ .reg .u64 t; cvta.to.shared.u64 t, %1; cvt.u32.u64 %0, t; }" : "=r"(a) : "l"(p));
    return a;
}
#define CP_ASYNC16(dst, src) \
    asm volatile("cp.async.cg.shared.global [%0], [%1], 16;" :: "r"(dst), "l"(src))
#define CP_COMMIT() asm volatile("cp.async.commit_group;" ::: "memory")
#define CP_WAIT0()  asm volatile("cp.async.wait_group 0;"  ::: "memory")

__device__ __forceinline__ void mma_tf32(float* c,
                                         unsigned a0, unsigned a1, unsigned a2, unsigned a3,
                                         unsigned b0, unsigned b1)
{
    asm volatile(
        "mma.sync.aligned.m16n8k8.row.col.f32.tf32.tf32.f32 "
        "{%0,%1,%2,%3}, {%4,%5,%6,%7}, {%8,%9}, {%0,%1,%2,%3};\n"
        : "+f"(c[0]), "+f"(c[1]), "+f"(c[2]), "+f"(c[3])
        : "r"(a0), "r"(a1), "r"(a2), "r"(a3), "r"(b0), "r"(b1));
}

// ---------------- weight tf32 pre-round (layout preserved [K][N]) ----------------
__global__ __launch_bounds__(256)
void round_w(const float* __restrict__ Wq, const float* __restrict__ Wk,
             const float* __restrict__ Wv, const float* __restrict__ Wo)
{
    const float* src = (blockIdx.y == 0) ? Wq : (blockIdx.y == 1) ? Wk
                     : (blockIdx.y == 2) ? Wv : Wo;
    float* dst = g_w + (size_t)blockIdx.y * WSZ;
    const size_t n4 = WSZ / 4;
    const size_t stride = (size_t)gridDim.x * blockDim.x;
    for (size_t i = (size_t)blockIdx.x * blockDim.x + threadIdx.x; i < n4; i += stride) {
        float4 v = ((const float4*)src)[i];
        v.x = f2tff(v.x); v.y = f2tff(v.y); v.z = f2tff(v.z); v.w = f2tff(v.w);
        ((float4*)dst)[i] = v;
    }
}

// ---------------- tf32 tensor-core GEMM (mma.sync, warp tile 64x64) ----------------
// C[M,N] = A[M,K] @ W[K,N] + bias. Block 128(M)x256(N), BK=16, 256 thr, 8 warps
// in 2(M)x4(N), warp tile 64x64 = 4x8 m16n8k8 atoms. B via cp.async from
// pre-rounded g_w (k-major rows). A via LDG+tf32+STS. 2-stage pipeline, 1 sync/iter.
#define BM   128
#define BN   256
#define BKD  16
#define ASTR 20          // conflict-free frag LDS & float4 STS (m-major)
#define BSTR 264         // 256+8
#define AFLOATS (BM * ASTR)          // 2560 floats per buffer
#define BFLOATS (BKD * BSTR)         // 4224 floats per buffer
#define ABYTES  (AFLOATS * 4)        // 10240
#define BBYTES  (BFLOATS * 4)        // 16896
#define SMEMB   (2 * ABYTES + 2 * BBYTES)   // 54272

__global__ __launch_bounds__(256, 1)
void tc_gemm(const float* __restrict__ A, int wbase,
             const float* __restrict__ b0, const float* __restrict__ b1,
             const float* __restrict__ b2,
             float* __restrict__ c0, float* __restrict__ c1, float* __restrict__ c2)
{
    extern __shared__ float smem[];
    const uint32_t sbase = smem_u32(smem);

    const int tid  = threadIdx.x;
    const int lane = tid & 31;
    const int wid  = tid >> 5;
    const int wm   = wid >> 2;          // 0..1 : warp M base wm*64
    const int wn   = wid & 3;           // 0..3 : warp N base wn*64
    const int lr   = lane >> 2;
    const int lc   = lane & 3;
    const int bm   = blockIdx.y * BM;
    const int bn   = blockIdx.x * BN;

    const float* W = g_w + (size_t)(wbase + blockIdx.z) * WSZ;
    const float* bias = (blockIdx.z == 0) ? b0 : (blockIdx.z == 1) ? b1 : b2;
    float* C = (blockIdx.z == 0) ? c0 : (blockIdx.z == 1) ? c1 : c2;

    // A loader: row arow (0..127), k-offset ak0 in {0,8}; two float4 per iter
    const int arow = tid >> 1;
    const int ak0  = (tid & 1) * 8;
    const float* Ap = A + (size_t)(bm + arow) * K_DIM + ak0;
    const uint32_t aSts = sbase + (uint32_t)(arow * ASTR + ak0) * 4u;

    // B loader: row brow (0..15), 4 x 16B chunks covering 16 floats
    const int brow = tid >> 4;
    const int bq   = (tid & 15) * 16;
    const float* Bp = W + (size_t)brow * N_DIM + bn + bq;
    const uint32_t bSts = sbase + 2u * ABYTES + (uint32_t)(brow * BSTR + bq) * 4u;

    float c[4][8][4];
    #pragma unroll
    for (int i = 0; i < 4; i++)
        #pragma unroll
        for (int j = 0; j < 8; j++)
            #pragma unroll
            for (int r = 0; r < 4; r++) c[i][j][r] = 0.0f;

    // ---- prologue: stage 0 ----
    {
        #pragma unroll
        for (int i = 0; i < 4; i++) CP_ASYNC16(bSts + i * 16u, Bp + i * 4);
        CP_COMMIT();
        float4 a0 = *(const float4*)(Ap);
        float4 a1 = *(const float4*)(Ap + 4);
        a0.x = f2tff(a0.x); a0.y = f2tff(a0.y); a0.z = f2tff(a0.z); a0.w = f2tff(a0.w);
        a1.x = f2tff(a1.x); a1.y = f2tff(a1.y); a1.z = f2tff(a1.z); a1.w = f2tff(a1.w);
        *(float4*)((char*)smem + (aSts - sbase))      = a0;
        *(float4*)((char*)smem + (aSts - sbase) + 16) = a1;
    }

    const int NK = K_DIM / BKD;   // 128
    for (int kt = 0; kt < NK; kt++) {
        const int cur = kt & 1;
        const int nb  = cur ^ 1;

        // prefetch next A into regs (overlaps wait + compute)
        float4 na0, na1;
        if (kt + 1 < NK) {
            const int kc = (kt + 1) * BKD;
            na0 = *(const float4*)(Ap + kc);
            na1 = *(const float4*)(Ap + kc + 4);
        }

        CP_WAIT0();          // B(kt) landed
        __syncthreads();     // A(kt) STS visible; all done computing buffer nb

        if (kt + 1 < NK) {   // issue B(kt+1) into nb
            const float* Bn = Bp + (size_t)(kt + 1) * BKD * N_DIM;
            const uint32_t d = bSts + (uint32_t)nb * BBYTES;
            #pragma unroll
            for (int i = 0; i < 4; i++) CP_ASYNC16(d + i * 16u, Bn + i * 4);
            CP_COMMIT();
        }

        // ---- compute on cur ----
        const float* Asb = smem + cur * AFLOATS;
        const float* Bsb = smem + 2 * AFLOATS + cur * BFLOATS;
        #pragma unroll
        for (int ks = 0; ks < 2; ks++) {
            const int k = ks * 8;
            unsigned af[4][4];
            #pragma unroll
            for (int i = 0; i < 4; i++) {
                const int m0 = wm * 64 + i * 16 + lr;
                af[i][0] = __float_as_uint(Asb[m0 * ASTR + k + lc]);
                af[i][1] = __float_as_uint(Asb[(m0 + 8) * ASTR + k + lc]);
                af[i][2] = __float_as_uint(Asb[m0 * ASTR + k + lc + 4]);
                af[i][3] = __float_as_uint(Asb[(m0 + 8) * ASTR + k + lc + 4]);
            }
            unsigned bf[8][2];
            #pragma unroll
            for (int j = 0; j < 8; j++) {
                const int n0 = wn * 64 + j * 8 + lr;
                bf[j][0] = __float_as_uint(Bsb[(k + lc) * BSTR + n0]);
                bf[j][1] = __float_as_uint(Bsb[(k + lc + 4) * BSTR + n0]);
            }
            #pragma unroll
            for (int i = 0; i < 4; i++)
                #pragma unroll
                for (int j = 0; j < 8; j++)
                    mma_tf32(c[i][j], af[i][0], af[i][1], af[i][2], af[i][3],
                             bf[j][0], bf[j][1]);
        }

        // stage A(kt+1) into nb (safe: nb compute finished by all at the sync above)
        if (kt + 1 < NK) {
            na0.x = f2tff(na0.x); na0.y = f2tff(na0.y); na0.z = f2tff(na0.z); na0.w = f2tff(na0.w);
            na1.x = f2tff(na1.x); na1.y = f2tff(na1.y); na1.z = f2tff(na1.z); na1.w = f2tff(na1.w);
            float* dst = smem + nb * AFLOATS + (arow * ASTR + ak0);
            *(float4*)(dst)     = na0;
            *(float4*)(dst + 4) = na1;
        }
    }

    // ---- epilogue: bias + float2 stores ----
    #pragma unroll
    for (int i = 0; i < 4; i++) {
        const int row0 = bm + wm * 64 + i * 16 + lr;
        #pragma unroll
        for (int j = 0; j < 8; j++) {
            const int col = bn + wn * 64 + j * 8 + 2 * lc;
            float2 bb = *(const float2*)(bias + col);
            float2 r0, r1;
            r0.x = c[i][j][0] + bb.x;  r0.y = c[i][j][1] + bb.y;
            r1.x = c[i][j][2] + bb.x;  r1.y = c[i][j][3] + bb.y;
            *(float2*)&C[(size_t)row0 * N_DIM + col]       = r0;
            *(float2*)&C[(size_t)(row0 + 8) * N_DIM + col] = r1;
        }
    }
}

// ---------------- fast exp ----------------
__device__ __forceinline__ float fast_exp(float x)
{
    float z  = x * 1.4426950408889634f;
    float fi = z + 12582912.0f;
    int   n  = __float_as_int(fi) - 0x4B400000;
    float f  = z - (fi - 12582912.0f);
    float p  = 1.3333558146e-3f;
    p = fmaf(p, f, 9.6181291918e-3f);
    p = fmaf(p, f, 5.5504108664e-2f);
    p = fmaf(p, f, 2.4022650695e-1f);
    p = fmaf(p, f, 6.9314718056e-1f);
    p = fmaf(p, f, 1.0f);
    return __int_as_float(__float_as_int(p) + (n << 23));
}

// ---------------- per-(b,s) head-mixing attention ----------------
// phase_shift is analytically dead (cos^2+sin^2=1; imaginary softmax discarded).
__global__ __launch_bounds__(256)
void attention_kernel()
{
    const int m = blockIdx.x;
    const int t = threadIdx.x;

    __shared__ float ks[N_DIM];
    __shared__ float vs[N_DIM];

    const float* qrow = g_q + (size_t)m * N_DIM;
    const float* krow = g_k + (size_t)m * N_DIM;
    const float* vrow = g_v + (size_t)m * N_DIM;

    *(float4*)&ks[t * 8]     = *(const float4*)&krow[t * 8];
    *(float4*)&ks[t * 8 + 4] = *(const float4*)&krow[t * 8 + 4];
    *(float4*)&vs[t * 8]     = *(const float4*)&vrow[t * 8];
    *(float4*)&vs[t * 8 + 4] = *(const float4*)&vrow[t * 8 + 4];

    const float scale = 0.35355339059327373f;   // 1/sqrt(8)
    float4 q0 = *(const float4*)&qrow[t * 8];
    float4 q1 = *(const float4*)&qrow[t * 8 + 4];
    q0.x *= scale; q0.y *= scale; q0.z *= scale; q0.w *= scale;
    q1.x *= scale; q1.y *= scale; q1.z *= scale; q1.w *= scale;

    __syncthreads();

    float sum = 0.0f;
    float4 o0 = {0.f, 0.f, 0.f, 0.f};
    float4 o1 = {0.f, 0.f, 0.f, 0.f};

    #pragma unroll 4
    for (int g = 0; g < HEADS; g++) {
        float4 k0 = *(const float4*)&ks[g * 8];
        float4 k1 = *(const float4*)&ks[g * 8 + 4];
        float s;
        s = q0.x * k0.x;
        s = fmaf(q0.y, k0.y, s);
        s = fmaf(q0.z, k0.z, s);
        s = fmaf(q0.w, k0.w, s);
        s = fmaf(q1.x, k1.x, s);
        s = fmaf(q1.y, k1.y, s);
        s = fmaf(q1.z, k1.z, s);
        s = fmaf(q1.w, k1.w, s);
        float p = fast_exp(s);
        sum += p;
        float4 v0 = *(const float4*)&vs[g * 8];
        float4 v1 = *(const float4*)&vs[g * 8 + 4];
        o0.x = fmaf(p, v0.x, o0.x);  o0.y = fmaf(p, v0.y, o0.y);
        o0.z = fmaf(p, v0.z, o0.z);  o0.w = fmaf(p, v0.w, o0.w);
        o1.x = fmaf(p, v1.x, o1.x);  o1.y = fmaf(p, v1.y, o1.y);
        o1.z = fmaf(p, v1.z, o1.z);  o1.w = fmaf(p, v1.w, o1.w);
    }

    const float inv = 1.0f / sum;
    o0.x *= inv; o0.y *= inv; o0.z *= inv; o0.w *= inv;
    o1.x *= inv; o1.y *= inv; o1.z *= inv; o1.w *= inv;
    *(float4*)&g_att[(size_t)m * N_DIM + t * 8]     = o0;
    *(float4*)&g_att[(size_t)m * N_DIM + t * 8 + 4] = o1;
}

// ---------------- launch ----------------
extern "C" void kernel_launch(void* const* d_in, const int* in_sizes, int n_in,
                              void* d_out, int out_size)
{
    const float* x  = (const float*)d_in[0];
    // d_in[1] = phase_shift: dead.
    const float* Wq = (const float*)d_in[2];
    const float* bq = (const float*)d_in[3];
    const float* Wk = (const float*)d_in[4];
    const float* bk = (const float*)d_in[5];
    const float* Wv = (const float*)d_in[6];
    const float* bv = (const float*)d_in[7];
    const float* Wo = (const float*)d_in[8];
    const float* bo = (const float*)d_in[9];
    float* out = (float*)d_out;

    void *pq, *pk, *pv, *patt;
    cudaGetSymbolAddress(&pq,  g_q);
    cudaGetSymbolAddress(&pk,  g_k);
    cudaGetSymbolAddress(&pv,  g_v);
    cudaGetSymbolAddress(&patt, g_att);

    cudaFuncSetAttribute(tc_gemm, cudaFuncAttributeMaxDynamicSharedMemorySize, SMEMB);

    round_w<<<dim3(512, 4), 256>>>(Wq, Wk, Wv, Wo);

    tc_gemm<<<dim3(N_DIM / BN, M_DIM / BM, 3), 256, SMEMB>>>(
        x, 0, bq, bk, bv, (float*)pq, (float*)pk, (float*)pv);

    attention_kernel<<<M_DIM, 256>>>();

    tc_gemm<<<dim3(N_DIM / BN, M_DIM / BM, 1), 256, SMEMB>>>(
        (const float*)patt, 3, bo, bo, bo, out, out, out);
}

// round 10
// speedup vs baseline: 1.1009x; 1.1009x over previous
#include <cuda_runtime.h>
#include <cuda_bf16.h>
#include <cstdint>

// Dims fixed: B=4, S=256, D_MODEL=2048, H=256, HEAD_DIM=8; M = B*S = 1024.
#define M_DIM 1024
#define N_DIM 2048
#define K_DIM 2048
#define HEADS 256

// ---------------- scratch ----------------
__device__ float g_q  [M_DIM * N_DIM];
__device__ float g_k  [M_DIM * N_DIM];
__device__ float g_v  [M_DIM * N_DIM];
__device__ float g_att[M_DIM * N_DIM];

// ---------------- tf32 tensor-core GEMM (mma.sync) ----------------
// C[M,N] = A[M,K] @ W[K,N] + bias. Block 128x128, BK=16, 128 threads
// (4 warps, 2x2), warp tile 64x64 = 4x8 m16n8k8 atoms.
// A smem m-major [128][20] (conflict-free frag LDS & float4 STS),
// B smem k-major [16][136]. One sync/iter. 2 CTAs/SM (128 thr -> 256-reg budget).
#define BK 16
#define ASTR 20
#define BSTR 136

__device__ __forceinline__ float f2tff(float x) {
    float r;
    asm("cvt.rna.tf32.f32 %0, %1;" : "=f"(r) : "f"(x));
    return r;
}

__device__ __forceinline__ void mma_tf32(float* c,
                                         unsigned a0, unsigned a1, unsigned a2, unsigned a3,
                                         unsigned b0, unsigned b1)
{
    asm volatile(
        "mma.sync.aligned.m16n8k8.row.col.f32.tf32.tf32.f32 "
        "{%0,%1,%2,%3}, {%4,%5,%6,%7}, {%8,%9}, {%0,%1,%2,%3};\n"
        : "+f"(c[0]), "+f"(c[1]), "+f"(c[2]), "+f"(c[3])
        : "r"(a0), "r"(a1), "r"(a2), "r"(a3), "r"(b0), "r"(b1));
}

__device__ __forceinline__ void gemm_body(const float* __restrict__ A,
                                          const float* __restrict__ W,
                                          const float* __restrict__ bias,
                                          float* __restrict__ C)
{
    __shared__ float As[2][128][ASTR];   // m-major: As[b][m][k]
    __shared__ float Bs[2][BK][BSTR];    // k-major: Bs[b][k][n]

    const int tid  = threadIdx.x;        // 0..127
    const int lane = tid & 31;
    const int wid  = tid >> 5;           // 0..3
    const int wm   = wid >> 1;           // 0..1 : warp M base wm*64
    const int wn   = wid & 1;            // 0..1 : warp N base wn*64
    const int lr   = lane >> 2;          // 0..7
    const int lc   = lane & 3;           // 0..3
    const int bm   = blockIdx.y * 128;
    const int bn   = blockIdx.x * 128;

    // A loader: thread t loads full row t of the 128x16 A tile (4 float4).
    const float* Ap = A + (size_t)(bm + tid) * K_DIM;
    // B loader: row rb (0..15), col chunks cb+{0,32,64,96} (4 float4, coalesced).
    const int rb = tid >> 3;
    const int cb = (tid & 7) * 4;
    const float* Bp = W + (size_t)rb * N_DIM + bn + cb;

    float c[4][8][4];
    #pragma unroll
    for (int i = 0; i < 4; i++)
        #pragma unroll
        for (int j = 0; j < 8; j++)
            #pragma unroll
            for (int r = 0; r < 4; r++) c[i][j][r] = 0.0f;

    float4 va[4], vb[4];

    // prologue: load chunk 0 into regs
    #pragma unroll
    for (int t = 0; t < 4; t++) va[t] = *(const float4*)(Ap + t * 4);
    #pragma unroll
    for (int t = 0; t < 4; t++) vb[t] = *(const float4*)(Bp + t * 32);

    const int NK = K_DIM / BK;   // 128
    for (int kt = 0; kt < NK; kt++) {
        const int cur = kt & 1;

        // STS (tf32-round on the fly), then ONE sync
        #pragma unroll
        for (int t = 0; t < 4; t++) {
            float4 a, b;
            a.x = f2tff(va[t].x); a.y = f2tff(va[t].y);
            a.z = f2tff(va[t].z); a.w = f2tff(va[t].w);
            b.x = f2tff(vb[t].x); b.y = f2tff(vb[t].y);
            b.z = f2tff(vb[t].z); b.w = f2tff(vb[t].w);
            *(float4*)&As[cur][tid][t * 4]      = a;
            *(float4*)&Bs[cur][rb][cb + t * 32] = b;
        }
        __syncthreads();

        // prefetch next chunk (overlaps compute)
        if (kt + 1 < NK) {
            const int kc = (kt + 1) * BK;
            #pragma unroll
            for (int t = 0; t < 4; t++) va[t] = *(const float4*)(Ap + kc + t * 4);
            #pragma unroll
            for (int t = 0; t < 4; t++) vb[t] = *(const float4*)(Bp + (size_t)kc * N_DIM + t * 32);
        }

        // compute: two k8 steps
        #pragma unroll
        for (int ks = 0; ks < 2; ks++) {
            const int k = ks * 8;
            unsigned af[4][4];
            #pragma unroll
            for (int i = 0; i < 4; i++) {
                const int m0 = wm * 64 + i * 16 + lr;
                af[i][0] = __float_as_uint(As[cur][m0    ][k + lc]);
                af[i][1] = __float_as_uint(As[cur][m0 + 8][k + lc]);
                af[i][2] = __float_as_uint(As[cur][m0    ][k + lc + 4]);
                af[i][3] = __float_as_uint(As[cur][m0 + 8][k + lc + 4]);
            }
            unsigned bf[8][2];
            #pragma unroll
            for (int j = 0; j < 8; j++) {
                const int n0 = wn * 64 + j * 8 + lr;
                bf[j][0] = __float_as_uint(Bs[cur][k + lc    ][n0]);
                bf[j][1] = __float_as_uint(Bs[cur][k + lc + 4][n0]);
            }
            #pragma unroll
            for (int i = 0; i < 4; i++)
                #pragma unroll
                for (int j = 0; j < 8; j++)
                    mma_tf32(c[i][j], af[i][0], af[i][1], af[i][2], af[i][3],
                             bf[j][0], bf[j][1]);
        }
    }

    // epilogue: bias + float2 stores (c0,c1 / c2,c3 are adjacent columns)
    #pragma unroll
    for (int i = 0; i < 4; i++) {
        const int row0 = bm + wm * 64 + i * 16 + lr;
        #pragma unroll
        for (int j = 0; j < 8; j++) {
            const int col = bn + wn * 64 + j * 8 + 2 * lc;
            float2 bb = *(const float2*)(bias + col);
            float2 r0, r1;
            r0.x = c[i][j][0] + bb.x;  r0.y = c[i][j][1] + bb.y;
            r1.x = c[i][j][2] + bb.x;  r1.y = c[i][j][3] + bb.y;
            *(float2*)&C[(size_t)row0 * N_DIM + col]       = r0;
            *(float2*)&C[(size_t)(row0 + 8) * N_DIM + col] = r1;
        }
    }
}

__global__ __launch_bounds__(128, 2)
void qkv_gemm(const float* __restrict__ x,
              const float* __restrict__ Wq, const float* __restrict__ bq,
              const float* __restrict__ Wk, const float* __restrict__ bk,
              const float* __restrict__ Wv, const float* __restrict__ bv)
{
    const float* W; const float* b; float* C;
    if (blockIdx.z == 0)      { W = Wq; b = bq; C = g_q; }
    else if (blockIdx.z == 1) { W = Wk; b = bk; C = g_k; }
    else                      { W = Wv; b = bv; C = g_v; }
    gemm_body(x, W, b, C);
}

__global__ __launch_bounds__(128, 2)
void o_gemm(const float* __restrict__ Wo, const float* __restrict__ bo,
            float* __restrict__ out)
{
    gemm_body(g_att, Wo, bo, out);
}

// ---------------- fast exp ----------------
__device__ __forceinline__ float fast_exp(float x)
{
    float z  = x * 1.4426950408889634f;
    float fi = z + 12582912.0f;
    int   n  = __float_as_int(fi) - 0x4B400000;
    float f  = z - (fi - 12582912.0f);
    float p  = 1.3333558146e-3f;
    p = fmaf(p, f, 9.6181291918e-3f);
    p = fmaf(p, f, 5.5504108664e-2f);
    p = fmaf(p, f, 2.4022650695e-1f);
    p = fmaf(p, f, 6.9314718056e-1f);
    p = fmaf(p, f, 1.0f);
    return __int_as_float(__float_as_int(p) + (n << 23));
}

// ---------------- per-(b,s) head-mixing attention ----------------
// phase_shift is analytically dead (cos^2+sin^2=1; imaginary softmax discarded).
__global__ __launch_bounds__(256)
void attention_kernel()
{
    const int m = blockIdx.x;
    const int t = threadIdx.x;

    __shared__ float ks[N_DIM];
    __shared__ float vs[N_DIM];

    const float* qrow = g_q + (size_t)m * N_DIM;
    const float* krow = g_k + (size_t)m * N_DIM;
    const float* vrow = g_v + (size_t)m * N_DIM;

    *(float4*)&ks[t * 8]     = *(const float4*)&krow[t * 8];
    *(float4*)&ks[t * 8 + 4] = *(const float4*)&krow[t * 8 + 4];
    *(float4*)&vs[t * 8]     = *(const float4*)&vrow[t * 8];
    *(float4*)&vs[t * 8 + 4] = *(const float4*)&vrow[t * 8 + 4];

    const float scale = 0.35355339059327373f;   // 1/sqrt(8)
    float4 q0 = *(const float4*)&qrow[t * 8];
    float4 q1 = *(const float4*)&qrow[t * 8 + 4];
    q0.x *= scale; q0.y *= scale; q0.z *= scale; q0.w *= scale;
    q1.x *= scale; q1.y *= scale; q1.z *= scale; q1.w *= scale;

    __syncthreads();

    float sum = 0.0f;
    float4 o0 = {0.f, 0.f, 0.f, 0.f};
    float4 o1 = {0.f, 0.f, 0.f, 0.f};

    #pragma unroll 4
    for (int g = 0; g < HEADS; g++) {
        float4 k0 = *(const float4*)&ks[g * 8];
        float4 k1 = *(const float4*)&ks[g * 8 + 4];
        float s;
        s = q0.x * k0.x;
        s = fmaf(q0.y, k0.y, s);
        s = fmaf(q0.z, k0.z, s);
        s = fmaf(q0.w, k0.w, s);
        s = fmaf(q1.x, k1.x, s);
        s = fmaf(q1.y, k1.y, s);
        s = fmaf(q1.z, k1.z, s);
        s = fmaf(q1.w, k1.w, s);
        float p = fast_exp(s);
        sum += p;
        float4 v0 = *(const float4*)&vs[g * 8];
        float4 v1 = *(const float4*)&vs[g * 8 + 4];
        o0.x = fmaf(p, v0.x, o0.x);  o0.y = fmaf(p, v0.y, o0.y);
        o0.z = fmaf(p, v0.z, o0.z);  o0.w = fmaf(p, v0.w, o0.w);
        o1.x = fmaf(p, v1.x, o1.x);  o1.y = fmaf(p, v1.y, o1.y);
        o1.z = fmaf(p, v1.z, o1.z);  o1.w = fmaf(p, v1.w, o1.w);
    }

    const float inv = 1.0f / sum;
    o0.x *= inv; o0.y *= inv; o0.z *= inv; o0.w *= inv;
    o1.x *= inv; o1.y *= inv; o1.z *= inv; o1.w *= inv;
    *(float4*)&g_att[(size_t)m * N_DIM + t * 8]     = o0;
    *(float4*)&g_att[(size_t)m * N_DIM + t * 8 + 4] = o1;
}

// ---------------- launch ----------------
extern "C" void kernel_launch(void* const* d_in, const int* in_sizes, int n_in,
                              void* d_out, int out_size)
{
    const float* x  = (const float*)d_in[0];
    // d_in[1] = phase_shift: dead.
    const float* Wq = (const float*)d_in[2];
    const float* bq = (const float*)d_in[3];
    const float* Wk = (const float*)d_in[4];
    const float* bk = (const float*)d_in[5];
    const float* Wv = (const float*)d_in[6];
    const float* bv = (const float*)d_in[7];
    const float* Wo = (const float*)d_in[8];
    const float* bo = (const float*)d_in[9];
    float* out = (float*)d_out;

    dim3 gQKV(N_DIM / 128, M_DIM / 128, 3);   // 16 x 8 x 3 = 384 blocks
    dim3 gO  (N_DIM / 128, M_DIM / 128, 1);   // 128 blocks

    qkv_gemm<<<gQKV, 128>>>(x, Wq, bq, Wk, bk, Wv, bv);
    attention_kernel<<<M_DIM, 256>>>();
    o_gemm<<<gO, 128>>>(Wo, bo, out);
}

// round 11
// speedup vs baseline: 1.6685x; 1.5155x over previous
#include <cuda_runtime.h>
#include <cuda_fp16.h>
#include <cstdint>

// Dims fixed: B=4, S=256, D_MODEL=2048, H=256, HEAD_DIM=8; M = B*S = 1024.
#define M_DIM 1024
#define N_DIM 2048
#define K_DIM 2048
#define HEADS 256

// ---------------- scratch ----------------
__device__ float g_q  [M_DIM * N_DIM];
__device__ float g_k  [M_DIM * N_DIM];
__device__ float g_v  [M_DIM * N_DIM];
__device__ float g_att[M_DIM * N_DIM];

// ---------------- fp16 tensor-core GEMM (mma.sync m16n8k16) ----------------
// C[M,N] = A[M,K] @ W[K,N] + bias, fp32 in/out, fp16 operands (11-bit mantissa,
// same as tf32), fp32 accumulate. Block 128x128, BK=16, 256 thr (8 warps 2x4),
// warp tile 64x32 (4x4 m16n8k16 atoms, one k16 step/iter).
// A smem: half [128][40] m-major (pad 40 -> frag LDS banks 20*lr+lc distinct).
// B smem: uint32 [8][136], word = half2(B[2kk][n], B[2kk+1][n]) so each B frag
// reg is ONE LDS.32 (banks 8*lc+lr distinct). One sync/iter, 2 CTAs/SM.
#define BK 16
#define ASTRH 40      // halves per A row (32 + 8 pad)
#define BSTRW 136     // words per B kk-row (128 + 8 pad)

__device__ __forceinline__ void mma_f16(float* c,
                                        unsigned a0, unsigned a1, unsigned a2, unsigned a3,
                                        unsigned b0, unsigned b1)
{
    asm volatile(
        "mma.sync.aligned.m16n8k16.row.col.f32.f16.f16.f32 "
        "{%0,%1,%2,%3}, {%4,%5,%6,%7}, {%8,%9}, {%0,%1,%2,%3};\n"
        : "+f"(c[0]), "+f"(c[1]), "+f"(c[2]), "+f"(c[3])
        : "r"(a0), "r"(a1), "r"(a2), "r"(a3), "r"(b0), "r"(b1));
}

__device__ __forceinline__ uint32_t pack2(float lo, float hi) {
    __half2 h = __floats2half2_rn(lo, hi);
    return *(uint32_t*)&h;
}

__device__ __forceinline__ void gemm_body(const float* __restrict__ A,
                                          const float* __restrict__ W,
                                          const float* __restrict__ bias,
                                          float* __restrict__ C)
{
    __shared__ __half  As[2][128][ASTRH];
    __shared__ uint32_t Bs[2][8][BSTRW];

    const int tid  = threadIdx.x;
    const int lane = tid & 31;
    const int wid  = tid >> 5;
    const int wm   = wid >> 2;          // 0..1 : warp M base wm*64
    const int wn   = wid & 3;           // 0..3 : warp N base wn*32
    const int lr   = lane >> 2;         // 0..7
    const int lc   = lane & 3;          // 0..3
    const int bm   = blockIdx.y * 128;
    const int bn   = blockIdx.x * 128;

    // A loader: row ar = tid>>1, k-offset ak = (tid&1)*8; 8 floats -> 8 halves,
    // one STS.128. Gmem: lanes pair up on rows -> 16 rows x 64B, coalesced.
    const int ar = tid >> 1;
    const int ak = (tid & 1) * 8;
    const float* Ap = A + (size_t)(bm + ar) * K_DIM + ak;

    // B loader: warp w handles kk = w (k rows 2w, 2w+1), lane covers 4 n's.
    // Packs k-pairs into half2 words, one STS.128. Gmem fully coalesced.
    const int kk = wid;                 // 0..7
    const int nb0 = lane * 4;           // 0..124
    const float* Bp = W + (size_t)(2 * kk) * N_DIM + bn + nb0;

    float c[4][4][4];
    #pragma unroll
    for (int i = 0; i < 4; i++)
        #pragma unroll
        for (int j = 0; j < 4; j++)
            #pragma unroll
            for (int r = 0; r < 4; r++) c[i][j][r] = 0.0f;

    float4 va0, va1, vb0, vb1;

    // prologue: load chunk 0
    va0 = *(const float4*)(Ap);
    va1 = *(const float4*)(Ap + 4);
    vb0 = *(const float4*)(Bp);
    vb1 = *(const float4*)(Bp + N_DIM);

    const int NK = K_DIM / BK;   // 128
    for (int kt = 0; kt < NK; kt++) {
        const int cur = kt & 1;

        // STS (cvt to fp16 / pack k-pairs), then ONE sync
        {
            uint4 aw, bw;
            aw.x = pack2(va0.x, va0.y);
            aw.y = pack2(va0.z, va0.w);
            aw.z = pack2(va1.x, va1.y);
            aw.w = pack2(va1.z, va1.w);
            bw.x = pack2(vb0.x, vb1.x);   // word n: (k=2kk, k=2kk+1)
            bw.y = pack2(vb0.y, vb1.y);
            bw.z = pack2(vb0.z, vb1.z);
            bw.w = pack2(vb0.w, vb1.w);
            *(uint4*)&As[cur][ar][ak]   = aw;
            *(uint4*)&Bs[cur][kk][nb0]  = bw;
        }
        __syncthreads();

        // prefetch next chunk (overlaps compute)
        if (kt + 1 < NK) {
            const int kc = (kt + 1) * BK;
            va0 = *(const float4*)(Ap + kc);
            va1 = *(const float4*)(Ap + kc + 4);
            vb0 = *(const float4*)(Bp + (size_t)kc * N_DIM);
            vb1 = *(const float4*)(Bp + (size_t)(kc + 1) * N_DIM);
        }

        // compute: one k16 step
        {
            unsigned af[4][4];
            #pragma unroll
            for (int i = 0; i < 4; i++) {
                const int m0 = wm * 64 + i * 16 + lr;
                const uint32_t* r0 = (const uint32_t*)&As[cur][m0][0];
                const uint32_t* r8 = (const uint32_t*)&As[cur][m0 + 8][0];
                af[i][0] = r0[lc];        // row m0,   k=2lc,2lc+1
                af[i][1] = r8[lc];        // row m0+8, k=2lc..
                af[i][2] = r0[lc + 4];    // row m0,   k=2lc+8..
                af[i][3] = r8[lc + 4];
            }
            unsigned bf[4][2];
            #pragma unroll
            for (int j = 0; j < 4; j++) {
                const int n0 = wn * 32 + j * 8 + lr;
                bf[j][0] = Bs[cur][lc][n0];       // k=2lc,2lc+1 @ n0
                bf[j][1] = Bs[cur][lc + 4][n0];   // k=2lc+8,+9 @ n0
            }
            #pragma unroll
            for (int i = 0; i < 4; i++)
                #pragma unroll
                for (int j = 0; j < 4; j++)
                    mma_f16(c[i][j], af[i][0], af[i][1], af[i][2], af[i][3],
                            bf[j][0], bf[j][1]);
        }
    }

    // epilogue: bias + float2 stores (c0,c1 / c2,c3 adjacent columns)
    #pragma unroll
    for (int i = 0; i < 4; i++) {
        const int row0 = bm + wm * 64 + i * 16 + lr;
        #pragma unroll
        for (int j = 0; j < 4; j++) {
            const int col = bn + wn * 32 + j * 8 + 2 * lc;
            float2 bb = *(const float2*)(bias + col);
            float2 r0, r1;
            r0.x = c[i][j][0] + bb.x;  r0.y = c[i][j][1] + bb.y;
            r1.x = c[i][j][2] + bb.x;  r1.y = c[i][j][3] + bb.y;
            *(float2*)&C[(size_t)row0 * N_DIM + col]       = r0;
            *(float2*)&C[(size_t)(row0 + 8) * N_DIM + col] = r1;
        }
    }
}

__global__ __launch_bounds__(256, 2)
void qkv_gemm(const float* __restrict__ x,
              const float* __restrict__ Wq, const float* __restrict__ bq,
              const float* __restrict__ Wk, const float* __restrict__ bk,
              const float* __restrict__ Wv, const float* __restrict__ bv)
{
    const float* W; const float* b; float* C;
    if (blockIdx.z == 0)      { W = Wq; b = bq; C = g_q; }
    else if (blockIdx.z == 1) { W = Wk; b = bk; C = g_k; }
    else                      { W = Wv; b = bv; C = g_v; }
    gemm_body(x, W, b, C);
}

__global__ __launch_bounds__(256, 2)
void o_gemm(const float* __restrict__ Wo, const float* __restrict__ bo,
            float* __restrict__ out)
{
    gemm_body(g_att, Wo, bo, out);
}

// ---------------- fast exp ----------------
__device__ __forceinline__ float fast_exp(float x)
{
    float z  = x * 1.4426950408889634f;
    float fi = z + 12582912.0f;
    int   n  = __float_as_int(fi) - 0x4B400000;
    float f  = z - (fi - 12582912.0f);
    float p  = 1.3333558146e-3f;
    p = fmaf(p, f, 9.6181291918e-3f);
    p = fmaf(p, f, 5.5504108664e-2f);
    p = fmaf(p, f, 2.4022650695e-1f);
    p = fmaf(p, f, 6.9314718056e-1f);
    p = fmaf(p, f, 1.0f);
    return __int_as_float(__float_as_int(p) + (n << 23));
}

// ---------------- per-(b,s) head-mixing attention ----------------
// phase_shift is analytically dead (cos^2+sin^2=1; imaginary softmax discarded).
__global__ __launch_bounds__(256)
void attention_kernel()
{
    const int m = blockIdx.x;
    const int t = threadIdx.x;

    __shared__ float ks[N_DIM];
    __shared__ float vs[N_DIM];

    const float* qrow = g_q + (size_t)m * N_DIM;
    const float* krow = g_k + (size_t)m * N_DIM;
    const float* vrow = g_v + (size_t)m * N_DIM;

    *(float4*)&ks[t * 8]     = *(const float4*)&krow[t * 8];
    *(float4*)&ks[t * 8 + 4] = *(const float4*)&krow[t * 8 + 4];
    *(float4*)&vs[t * 8]     = *(const float4*)&vrow[t * 8];
    *(float4*)&vs[t * 8 + 4] = *(const float4*)&vrow[t * 8 + 4];

    const float scale = 0.35355339059327373f;   // 1/sqrt(8)
    float4 q0 = *(const float4*)&qrow[t * 8];
    float4 q1 = *(const float4*)&qrow[t * 8 + 4];
    q0.x *= scale; q0.y *= scale; q0.z *= scale; q0.w *= scale;
    q1.x *= scale; q1.y *= scale; q1.z *= scale; q1.w *= scale;

    __syncthreads();

    float sum = 0.0f;
    float4 o0 = {0.f, 0.f, 0.f, 0.f};
    float4 o1 = {0.f, 0.f, 0.f, 0.f};

    #pragma unroll 4
    for (int g = 0; g < HEADS; g++) {
        float4 k0 = *(const float4*)&ks[g * 8];
        float4 k1 = *(const float4*)&ks[g * 8 + 4];
        float s;
        s = q0.x * k0.x;
        s = fmaf(q0.y, k0.y, s);
        s = fmaf(q0.z, k0.z, s);
        s = fmaf(q0.w, k0.w, s);
        s = fmaf(q1.x, k1.x, s);
        s = fmaf(q1.y, k1.y, s);
        s = fmaf(q1.z, k1.z, s);
        s = fmaf(q1.w, k1.w, s);
        float p = fast_exp(s);
        sum += p;
        float4 v0 = *(const float4*)&vs[g * 8];
        float4 v1 = *(const float4*)&vs[g * 8 + 4];
        o0.x = fmaf(p, v0.x, o0.x);  o0.y = fmaf(p, v0.y, o0.y);
        o0.z = fmaf(p, v0.z, o0.z);  o0.w = fmaf(p, v0.w, o0.w);
        o1.x = fmaf(p, v1.x, o1.x);  o1.y = fmaf(p, v1.y, o1.y);
        o1.z = fmaf(p, v1.z, o1.z);  o1.w = fmaf(p, v1.w, o1.w);
    }

    const float inv = 1.0f / sum;
    o0.x *= inv; o0.y *= inv; o0.z *= inv; o0.w *= inv;
    o1.x *= inv; o1.y *= inv; o1.z *= inv; o1.w *= inv;
    *(float4*)&g_att[(size_t)m * N_DIM + t * 8]     = o0;
    *(float4*)&g_att[(size_t)m * N_DIM + t * 8 + 4] = o1;
}

// ---------------- launch ----------------
extern "C" void kernel_launch(void* const* d_in, const int* in_sizes, int n_in,
                              void* d_out, int out_size)
{
    const float* x  = (const float*)d_in[0];
    // d_in[1] = phase_shift: dead.
    const float* Wq = (const float*)d_in[2];
    const float* bq = (const float*)d_in[3];
    const float* Wk = (const float*)d_in[4];
    const float* bk = (const float*)d_in[5];
    const float* Wv = (const float*)d_in[6];
    const float* bv = (const float*)d_in[7];
    const float* Wo = (const float*)d_in[8];
    const float* bo = (const float*)d_in[9];
    float* out = (float*)d_out;

    dim3 gQKV(N_DIM / 128, M_DIM / 128, 3);   // 16 x 8 x 3 = 384 blocks
    dim3 gO  (N_DIM / 128, M_DIM / 128, 1);   // 128 blocks

    qkv_gemm<<<gQKV, 256>>>(x, Wq, bq, Wk, bk, Wv, bv);
    attention_kernel<<<M_DIM, 256>>>();
    o_gemm<<<gO, 256>>>(Wo, bo, out);
}

// round 12
// speedup vs baseline: 2.1002x; 1.2587x over previous
#include <cuda_runtime.h>
#include <cuda_fp16.h>
#include <cstdint>

// Dims fixed: B=4, S=256, D_MODEL=2048, H=256, HEAD_DIM=8; M = B*S = 1024.
#define M_DIM 1024
#define N_DIM 2048
#define K_DIM 2048
#define HEADS 256
#define K2DIM (K_DIM / 2)

// ---------------- scratch ----------------
__device__ float    g_q  [M_DIM * N_DIM];
__device__ float    g_k  [M_DIM * N_DIM];
__device__ float    g_v  [M_DIM * N_DIM];
__device__ __half   g_att[M_DIM * N_DIM];                    // attention out, fp16
__device__ __half   g_xh [M_DIM * K_DIM];                    // x as fp16
__device__ uint32_t g_wh [4 * (size_t)K2DIM * N_DIM];        // W as k-pair-packed half2

// ---------------- helpers ----------------
__device__ __forceinline__ uint32_t pack2(float lo, float hi) {
    __half2 h = __floats2half2_rn(lo, hi);
    return *(uint32_t*)&h;
}
__device__ __forceinline__ uint32_t smem_u32(const void* p) {
    uint32_t a;
    asm("{ .reg .u64 t; cvta.to.shared.u64 t, %1; cvt.u32.u64 %0, t; }" : "=r"(a) : "l"(p));
    return a;
}
#define CP_ASYNC16(dst, src) \
    asm volatile("cp.async.cg.shared.global [%0], [%1], 16;" :: "r"(dst), "l"(src))
#define CP_COMMIT() asm volatile("cp.async.commit_group;" ::: "memory")
#define CP_WAIT0()  asm volatile("cp.async.wait_group 0;"  ::: "memory")
#define CP_WAIT1()  asm volatile("cp.async.wait_group 1;"  ::: "memory")

__device__ __forceinline__ void mma_f16(float* c,
                                        unsigned a0, unsigned a1, unsigned a2, unsigned a3,
                                        unsigned b0, unsigned b1)
{
    asm volatile(
        "mma.sync.aligned.m16n8k16.row.col.f32.f16.f16.f32 "
        "{%0,%1,%2,%3}, {%4,%5,%6,%7}, {%8,%9}, {%0,%1,%2,%3};\n"
        : "+f"(c[0]), "+f"(c[1]), "+f"(c[2]), "+f"(c[3])
        : "r"(a0), "r"(a1), "r"(a2), "r"(a3), "r"(b0), "r"(b1));
}

// f32x2 packed fp32 math (PTX sm_100+; dual-issue FFMA)
typedef unsigned long long ull;
__device__ __forceinline__ ull pk2f(float x, float y) {
    ull r; asm("mov.b64 %0, {%1, %2};" : "=l"(r) : "f"(x), "f"(y)); return r;
}
#define FMAX2(d, a, b, c) \
    asm("fma.rn.f32x2 %0, %1, %2, %3;" : "=l"(d) : "l"(a), "l"(b), "l"(c))
#define MULX2(d, a, b) \
    asm("mul.rn.f32x2 %0, %1, %2;" : "=l"(d) : "l"(a), "l"(b))
#define UPKX2(x, y, v) \
    asm("mov.b64 {%0, %1}, %2;" : "=f"(x), "=f"(y) : "l"(v))

// ---------------- prepass: convert W and x to fp16 ----------------
// g_wh[z][k2][n] = half2(W[2k2][n], W[2k2+1][n])  — exactly the GEMM smem word.
__global__ __launch_bounds__(256)
void cvt_w(const float* __restrict__ Wq, const float* __restrict__ Wk,
           const float* __restrict__ Wv, const float* __restrict__ Wo)
{
    const float* W = (blockIdx.y == 0) ? Wq : (blockIdx.y == 1) ? Wk
                   : (blockIdx.y == 2) ? Wv : Wo;
    uint32_t* D = g_wh + (size_t)blockIdx.y * K2DIM * N_DIM;
    const int idx = blockIdx.x * blockDim.x + threadIdx.x;   // 0 .. 1024*512-1
    const int k2  = idx >> 9;
    const int nc  = (idx & 511) * 4;
    const float* r0 = W + (size_t)(2 * k2) * N_DIM + nc;
    float4 a = *(const float4*)r0;
    float4 b = *(const float4*)(r0 + N_DIM);
    uint4 o;
    o.x = pack2(a.x, b.x); o.y = pack2(a.y, b.y);
    o.z = pack2(a.z, b.z); o.w = pack2(a.w, b.w);
    *(uint4*)&D[(size_t)k2 * N_DIM + nc] = o;
}

__global__ __launch_bounds__(256)
void cvt_x(const float* __restrict__ x)
{
    const int idx = blockIdx.x * blockDim.x + threadIdx.x;   // 0 .. 262143
    const float* s = x + (size_t)idx * 8;
    float4 a = *(const float4*)s;
    float4 b = *(const float4*)(s + 4);
    uint4 o;
    o.x = pack2(a.x, a.y); o.y = pack2(a.z, a.w);
    o.z = pack2(b.x, b.y); o.w = pack2(b.z, b.w);
    *(uint4*)&g_xh[(size_t)idx * 8] = o;
}

// ---------------- fp16 GEMM, cp.async 3-stage pipeline ----------------
// C[M,N] = A[M,K] @ W[K,N] + bias; A fp16 row-major halves, W = g_wh packed.
// Block 128x128, BK=16 (8 k-pairs), 256 thr, 8 warps 2x4, warp tile 64x32.
// A smem: per row 8 data words + 4 pad (stride 48B) -> frag LDS conflict-free
// (banks 12*lr mod 32 = {0,4,...,28} spaced 4, +lc covers all 32).
// B smem: [8][136] words (stride mod 32 = 8 -> 8lc+lr distinct). 1 sync/iter.
#define NKCH  (K_DIM / 16)   // 128 chunks
#define ABUF  6144           // 128 rows * 48 B
#define BBUF  4352           // 8 * 136 * 4 B
#define STG_B (ABUF + BBUF)  // 10496

__device__ __forceinline__ void gemm_body(const __half* __restrict__ A,
                                          const uint32_t* __restrict__ Bw,
                                          const float* __restrict__ bias,
                                          float* __restrict__ C)
{
    __shared__ __align__(16) char sm[3 * STG_B];
    const uint32_t sb = smem_u32(sm);

    const int tid  = threadIdx.x;
    const int lane = tid & 31;
    const int wid  = tid >> 5;
    const int wm   = wid >> 2;          // warp M base wm*64
    const int wn   = wid & 3;           // warp N base wn*32
    const int lr   = lane >> 2;
    const int lc   = lane & 3;
    const int bm   = blockIdx.y * 128;
    const int bn   = blockIdx.x * 128;

    // A cp.async: row ar, 16B piece ah (row = 32B of halves)
    const int ar = tid >> 1, ah = tid & 1;
    const __half* Asrc = A + (size_t)(bm + ar) * K_DIM + ah * 8;
    const uint32_t aOff = (uint32_t)(ar * 48 + ah * 16);
    // B cp.async: k-pair row kk, word chunk wq (warp covers one full row)
    const int kk = tid >> 5;
    const int wq = lane * 4;
    const uint32_t* Bsrc = Bw + (size_t)kk * N_DIM + bn + wq;
    const uint32_t bOff = (uint32_t)(ABUF + kk * 544 + wq * 4);

    float c[4][4][4];
    #pragma unroll
    for (int i = 0; i < 4; i++)
        #pragma unroll
        for (int j = 0; j < 4; j++)
            #pragma unroll
            for (int r = 0; r < 4; r++) c[i][j][r] = 0.0f;

    // prologue: issue chunks 0,1 into stages 0,1
    #pragma unroll
    for (int p = 0; p < 2; p++) {
        const uint32_t base = sb + p * STG_B;
        CP_ASYNC16(base + aOff, Asrc + (size_t)p * 16);
        CP_ASYNC16(base + bOff, Bsrc + (size_t)p * 8 * N_DIM);
        CP_COMMIT();
    }

    for (int kt = 0; kt < NKCH; kt++) {
        const int s = kt % 3;
        if (kt < NKCH - 1) { CP_WAIT1(); } else { CP_WAIT0(); }
        __syncthreads();

        const char* aP = sm + s * STG_B;
        const char* bP = aP + ABUF;

        unsigned af[4][4];
        #pragma unroll
        for (int i = 0; i < 4; i++) {
            const int m0 = wm * 64 + i * 16 + lr;
            const uint32_t* r0 = (const uint32_t*)(aP + m0 * 48);
            const uint32_t* r8 = (const uint32_t*)(aP + (m0 + 8) * 48);
            af[i][0] = r0[lc];
            af[i][1] = r8[lc];
            af[i][2] = r0[lc + 4];
            af[i][3] = r8[lc + 4];
        }
        unsigned bf[4][2];
        #pragma unroll
        for (int j = 0; j < 4; j++) {
            const int n0 = wn * 32 + j * 8 + lr;
            bf[j][0] = ((const uint32_t*)(bP + lc * 544))[n0];
            bf[j][1] = ((const uint32_t*)(bP + (lc + 4) * 544))[n0];
        }
        #pragma unroll
        for (int i = 0; i < 4; i++)
            #pragma unroll
            for (int j = 0; j < 4; j++)
                mma_f16(c[i][j], af[i][0], af[i][1], af[i][2], af[i][3],
                        bf[j][0], bf[j][1]);

        // issue chunk kt+2 into stage (kt+2)%3 (freed: computed at iter kt-1;
        // all threads passed this iter's barrier => done with it)
        if (kt + 2 < NKCH) {
            const int ns = (kt + 2) % 3;
            const uint32_t base = sb + ns * STG_B;
            CP_ASYNC16(base + aOff, Asrc + (size_t)(kt + 2) * 16);
            CP_ASYNC16(base + bOff, Bsrc + (size_t)(kt + 2) * 8 * N_DIM);
            CP_COMMIT();
        }
    }

    // epilogue: bias + float2 stores
    #pragma unroll
    for (int i = 0; i < 4; i++) {
        const int row0 = bm + wm * 64 + i * 16 + lr;
        #pragma unroll
        for (int j = 0; j < 4; j++) {
            const int col = bn + wn * 32 + j * 8 + 2 * lc;
            float2 bb = *(const float2*)(bias + col);
            float2 r0, r1;
            r0.x = c[i][j][0] + bb.x;  r0.y = c[i][j][1] + bb.y;
            r1.x = c[i][j][2] + bb.x;  r1.y = c[i][j][3] + bb.y;
            *(float2*)&C[(size_t)row0 * N_DIM + col]       = r0;
            *(float2*)&C[(size_t)(row0 + 8) * N_DIM + col] = r1;
        }
    }
}

__global__ __launch_bounds__(256, 2)
void qkv_gemm(const float* __restrict__ bq, const float* __restrict__ bk,
              const float* __restrict__ bv)
{
    const int z = blockIdx.z;
    const float* bias = (z == 0) ? bq : (z == 1) ? bk : bv;
    float* C = (z == 0) ? g_q : (z == 1) ? g_k : g_v;
    gemm_body(g_xh, g_wh + (size_t)z * K2DIM * N_DIM, bias, C);
}

__global__ __launch_bounds__(256, 2)
void o_gemm(const float* __restrict__ bo, float* __restrict__ out)
{
    gemm_body(g_att, g_wh + (size_t)3 * K2DIM * N_DIM, bo, out);
}

// ---------------- fast exp ----------------
__device__ __forceinline__ float fast_exp(float x)
{
    float z  = x * 1.4426950408889634f;
    float fi = z + 12582912.0f;
    int   n  = __float_as_int(fi) - 0x4B400000;
    float f  = z - (fi - 12582912.0f);
    float p  = 1.3333558146e-3f;
    p = fmaf(p, f, 9.6181291918e-3f);
    p = fmaf(p, f, 5.5504108664e-2f);
    p = fmaf(p, f, 2.4022650695e-1f);
    p = fmaf(p, f, 6.9314718056e-1f);
    p = fmaf(p, f, 1.0f);
    return __int_as_float(__float_as_int(p) + (n << 23));
}

// ---------------- per-(b,s) head-mixing attention (f32x2, fp16 out) ----------------
// phase_shift is analytically dead (cos^2+sin^2=1; imaginary softmax discarded).
__global__ __launch_bounds__(256)
void attention_kernel()
{
    const int m = blockIdx.x;
    const int t = threadIdx.x;

    __shared__ float ks[N_DIM];
    __shared__ float vs[N_DIM];

    const float* qrow = g_q + (size_t)m * N_DIM;
    const float* krow = g_k + (size_t)m * N_DIM;
    const float* vrow = g_v + (size_t)m * N_DIM;

    *(float4*)&ks[t * 8]     = *(const float4*)&krow[t * 8];
    *(float4*)&ks[t * 8 + 4] = *(const float4*)&krow[t * 8 + 4];
    *(float4*)&vs[t * 8]     = *(const float4*)&vrow[t * 8];
    *(float4*)&vs[t * 8 + 4] = *(const float4*)&vrow[t * 8 + 4];

    const float scale = 0.35355339059327373f;   // 1/sqrt(8)
    float4 q0 = *(const float4*)&qrow[t * 8];
    float4 q1 = *(const float4*)&qrow[t * 8 + 4];
    const ull q01 = pk2f(q0.x * scale, q0.y * scale);
    const ull q23 = pk2f(q0.z * scale, q0.w * scale);
    const ull q45 = pk2f(q1.x * scale, q1.y * scale);
    const ull q67 = pk2f(q1.z * scale, q1.w * scale);

    __syncthreads();

    float sum = 0.0f;
    ull o01 = 0, o23 = 0, o45 = 0, o67 = 0;   // bit-0 == (0.0f, 0.0f)

    #pragma unroll 4
    for (int g = 0; g < HEADS; g++) {
        const ulonglong2 ka = *(const ulonglong2*)&ks[g * 8];
        const ulonglong2 kb = *(const ulonglong2*)&ks[g * 8 + 4];
        ull s2;
        MULX2(s2, q01, ka.x);
        FMAX2(s2, q23, ka.y, s2);
        FMAX2(s2, q45, kb.x, s2);
        FMAX2(s2, q67, kb.y, s2);
        float sx, sy; UPKX2(sx, sy, s2);
        const float p = fast_exp(sx + sy);
        sum += p;
        const ull pp = pk2f(p, p);
        const ulonglong2 va = *(const ulonglong2*)&vs[g * 8];
        const ulonglong2 vb = *(const ulonglong2*)&vs[g * 8 + 4];
        FMAX2(o01, pp, va.x, o01);
        FMAX2(o23, pp, va.y, o23);
        FMAX2(o45, pp, vb.x, o45);
        FMAX2(o67, pp, vb.y, o67);
    }

    const float inv = 1.0f / sum;
    const ull iv = pk2f(inv, inv);
    MULX2(o01, o01, iv);
    MULX2(o23, o23, iv);
    MULX2(o45, o45, iv);
    MULX2(o67, o67, iv);

    float a, b;
    uint4 st;
    UPKX2(a, b, o01); st.x = pack2(a, b);
    UPKX2(a, b, o23); st.y = pack2(a, b);
    UPKX2(a, b, o45); st.z = pack2(a, b);
    UPKX2(a, b, o67); st.w = pack2(a, b);
    *(uint4*)&g_att[(size_t)m * N_DIM + t * 8] = st;
}

// ---------------- launch ----------------
extern "C" void kernel_launch(void* const* d_in, const int* in_sizes, int n_in,
                              void* d_out, int out_size)
{
    const float* x  = (const float*)d_in[0];
    // d_in[1] = phase_shift: dead.
    const float* Wq = (const float*)d_in[2];
    const float* bq = (const float*)d_in[3];
    const float* Wk = (const float*)d_in[4];
    const float* bk = (const float*)d_in[5];
    const float* Wv = (const float*)d_in[6];
    const float* bv = (const float*)d_in[7];
    const float* Wo = (const float*)d_in[8];
    const float* bo = (const float*)d_in[9];
    float* out = (float*)d_out;

    cvt_w<<<dim3(2048, 4), 256>>>(Wq, Wk, Wv, Wo);
    cvt_x<<<1024, 256>>>(x);
    qkv_gemm<<<dim3(N_DIM / 128, M_DIM / 128, 3), 256>>>(bq, bk, bv);
    attention_kernel<<<M_DIM, 256>>>();
    o_gemm<<<dim3(N_DIM / 128, M_DIM / 128, 1), 256>>>(bo, out);
}

// round 13
// speedup vs baseline: 2.1686x; 1.0326x over previous
#include <cuda_runtime.h>
#include <cuda_fp16.h>
#include <cstdint>

// Dims fixed: B=4, S=256, D_MODEL=2048, H=256, HEAD_DIM=8; M = B*S = 1024.
#define M_DIM 1024
#define N_DIM 2048
#define K_DIM 2048
#define HEADS 256
#define K2DIM (K_DIM / 2)

// ---------------- scratch ----------------
__device__ float    g_q  [M_DIM * N_DIM];
__device__ float    g_k  [M_DIM * N_DIM];
__device__ float    g_v  [M_DIM * N_DIM];
__device__ __half   g_att[M_DIM * N_DIM];                    // attention out, fp16
__device__ __half   g_xh [M_DIM * K_DIM];                    // x as fp16
__device__ uint32_t g_wh [4 * (size_t)K2DIM * N_DIM];        // W as k-pair-packed half2

// ---------------- helpers ----------------
__device__ __forceinline__ uint32_t pack2(float lo, float hi) {
    __half2 h = __floats2half2_rn(lo, hi);
    return *(uint32_t*)&h;
}
__device__ __forceinline__ uint32_t smem_u32(const void* p) {
    uint32_t a;
    asm("{ .reg .u64 t; cvta.to.shared.u64 t, %1; cvt.u32.u64 %0, t; }" : "=r"(a) : "l"(p));
    return a;
}
#define CP_ASYNC16(dst, src) \
    asm volatile("cp.async.cg.shared.global [%0], [%1], 16;" :: "r"(dst), "l"(src))
#define CP_COMMIT() asm volatile("cp.async.commit_group;" ::: "memory")
#define CP_WAIT0()  asm volatile("cp.async.wait_group 0;"  ::: "memory")
#define CP_WAIT1()  asm volatile("cp.async.wait_group 1;"  ::: "memory")

__device__ __forceinline__ void mma_f16(float* c,
                                        unsigned a0, unsigned a1, unsigned a2, unsigned a3,
                                        unsigned b0, unsigned b1)
{
    asm volatile(
        "mma.sync.aligned.m16n8k16.row.col.f32.f16.f16.f32 "
        "{%0,%1,%2,%3}, {%4,%5,%6,%7}, {%8,%9}, {%0,%1,%2,%3};\n"
        : "+f"(c[0]), "+f"(c[1]), "+f"(c[2]), "+f"(c[3])
        : "r"(a0), "r"(a1), "r"(a2), "r"(a3), "r"(b0), "r"(b1));
}

// f32x2 packed fp32 math (PTX sm_100+; dual-issue FFMA)
typedef unsigned long long ull;
__device__ __forceinline__ ull pk2f(float x, float y) {
    ull r; asm("mov.b64 %0, {%1, %2};" : "=l"(r) : "f"(x), "f"(y)); return r;
}
#define FMAX2(d, a, b, c) \
    asm("fma.rn.f32x2 %0, %1, %2, %3;" : "=l"(d) : "l"(a), "l"(b), "l"(c))
#define MULX2(d, a, b) \
    asm("mul.rn.f32x2 %0, %1, %2;" : "=l"(d) : "l"(a), "l"(b))
#define UPKX2(x, y, v) \
    asm("mov.b64 {%0, %1}, %2;" : "=f"(x), "=f"(y) : "l"(v))

// ---------------- prepass: convert W and x to fp16 (one launch) ----------------
// g_wh[z][k2][n] = half2(W[2k2][n], W[2k2+1][n])  — exactly the GEMM smem word.
__global__ __launch_bounds__(256)
void cvt_all(const float* __restrict__ x,
             const float* __restrict__ Wq, const float* __restrict__ Wk,
             const float* __restrict__ Wv, const float* __restrict__ Wo)
{
    if (blockIdx.y < 4) {
        const float* W = (blockIdx.y == 0) ? Wq : (blockIdx.y == 1) ? Wk
                       : (blockIdx.y == 2) ? Wv : Wo;
        uint32_t* D = g_wh + (size_t)blockIdx.y * K2DIM * N_DIM;
        const int idx = blockIdx.x * blockDim.x + threadIdx.x;
        const int k2  = idx >> 9;
        const int nc  = (idx & 511) * 4;
        const float* r0 = W + (size_t)(2 * k2) * N_DIM + nc;
        float4 a = *(const float4*)r0;
        float4 b = *(const float4*)(r0 + N_DIM);
        uint4 o;
        o.x = pack2(a.x, b.x); o.y = pack2(a.y, b.y);
        o.z = pack2(a.z, b.z); o.w = pack2(a.w, b.w);
        *(uint4*)&D[(size_t)k2 * N_DIM + nc] = o;
    } else if (blockIdx.x < 1024) {
        const int idx = blockIdx.x * blockDim.x + threadIdx.x;
        const float* s = x + (size_t)idx * 8;
        float4 a = *(const float4*)s;
        float4 b = *(const float4*)(s + 4);
        uint4 o;
        o.x = pack2(a.x, a.y); o.y = pack2(a.z, a.w);
        o.z = pack2(b.x, b.y); o.w = pack2(b.z, b.w);
        *(uint4*)&g_xh[(size_t)idx * 8] = o;
    }
}

// ---------------- fp16 GEMM, cp.async 3-stage pipeline ----------------
#define NKCH  (K_DIM / 16)   // 128 chunks
#define ABUF  6144           // 128 rows * 48 B
#define BBUF  4352           // 8 * 136 * 4 B
#define STG_B (ABUF + BBUF)  // 10496

__device__ __forceinline__ void gemm_body(const __half* __restrict__ A,
                                          const uint32_t* __restrict__ Bw,
                                          const float* __restrict__ bias,
                                          float* __restrict__ C)
{
    __shared__ __align__(16) char sm[3 * STG_B];
    const uint32_t sb = smem_u32(sm);

    const int tid  = threadIdx.x;
    const int lane = tid & 31;
    const int wid  = tid >> 5;
    const int wm   = wid >> 2;
    const int wn   = wid & 3;
    const int lr   = lane >> 2;
    const int lc   = lane & 3;
    const int bm   = blockIdx.y * 128;
    const int bn   = blockIdx.x * 128;

    const int ar = tid >> 1, ah = tid & 1;
    const __half* Asrc = A + (size_t)(bm + ar) * K_DIM + ah * 8;
    const uint32_t aOff = (uint32_t)(ar * 48 + ah * 16);
    const int kk = tid >> 5;
    const int wq = lane * 4;
    const uint32_t* Bsrc = Bw + (size_t)kk * N_DIM + bn + wq;
    const uint32_t bOff = (uint32_t)(ABUF + kk * 544 + wq * 4);

    float c[4][4][4];
    #pragma unroll
    for (int i = 0; i < 4; i++)
        #pragma unroll
        for (int j = 0; j < 4; j++)
            #pragma unroll
            for (int r = 0; r < 4; r++) c[i][j][r] = 0.0f;

    #pragma unroll
    for (int p = 0; p < 2; p++) {
        const uint32_t base = sb + p * STG_B;
        CP_ASYNC16(base + aOff, Asrc + (size_t)p * 16);
        CP_ASYNC16(base + bOff, Bsrc + (size_t)p * 8 * N_DIM);
        CP_COMMIT();
    }

    for (int kt = 0; kt < NKCH; kt++) {
        const int s = kt % 3;
        if (kt < NKCH - 1) { CP_WAIT1(); } else { CP_WAIT0(); }
        __syncthreads();

        const char* aP = sm + s * STG_B;
        const char* bP = aP + ABUF;

        unsigned af[4][4];
        #pragma unroll
        for (int i = 0; i < 4; i++) {
            const int m0 = wm * 64 + i * 16 + lr;
            const uint32_t* r0 = (const uint32_t*)(aP + m0 * 48);
            const uint32_t* r8 = (const uint32_t*)(aP + (m0 + 8) * 48);
            af[i][0] = r0[lc];
            af[i][1] = r8[lc];
            af[i][2] = r0[lc + 4];
            af[i][3] = r8[lc + 4];
        }
        unsigned bf[4][2];
        #pragma unroll
        for (int j = 0; j < 4; j++) {
            const int n0 = wn * 32 + j * 8 + lr;
            bf[j][0] = ((const uint32_t*)(bP + lc * 544))[n0];
            bf[j][1] = ((const uint32_t*)(bP + (lc + 4) * 544))[n0];
        }
        #pragma unroll
        for (int i = 0; i < 4; i++)
            #pragma unroll
            for (int j = 0; j < 4; j++)
                mma_f16(c[i][j], af[i][0], af[i][1], af[i][2], af[i][3],
                        bf[j][0], bf[j][1]);

        if (kt + 2 < NKCH) {
            const int ns = (kt + 2) % 3;
            const uint32_t base = sb + ns * STG_B;
            CP_ASYNC16(base + aOff, Asrc + (size_t)(kt + 2) * 16);
            CP_ASYNC16(base + bOff, Bsrc + (size_t)(kt + 2) * 8 * N_DIM);
            CP_COMMIT();
        }
    }

    #pragma unroll
    for (int i = 0; i < 4; i++) {
        const int row0 = bm + wm * 64 + i * 16 + lr;
        #pragma unroll
        for (int j = 0; j < 4; j++) {
            const int col = bn + wn * 32 + j * 8 + 2 * lc;
            float2 bb = *(const float2*)(bias + col);
            float2 r0, r1;
            r0.x = c[i][j][0] + bb.x;  r0.y = c[i][j][1] + bb.y;
            r1.x = c[i][j][2] + bb.x;  r1.y = c[i][j][3] + bb.y;
            *(float2*)&C[(size_t)row0 * N_DIM + col]       = r0;
            *(float2*)&C[(size_t)(row0 + 8) * N_DIM + col] = r1;
        }
    }
}

__global__ __launch_bounds__(256, 2)
void qkv_gemm(const float* __restrict__ bq, const float* __restrict__ bk,
              const float* __restrict__ bv)
{
    const int z = blockIdx.z;
    const float* bias = (z == 0) ? bq : (z == 1) ? bk : bv;
    float* C = (z == 0) ? g_q : (z == 1) ? g_k : g_v;
    gemm_body(g_xh, g_wh + (size_t)z * K2DIM * N_DIM, bias, C);
}

__global__ __launch_bounds__(256, 2)
void o_gemm(const float* __restrict__ bo, float* __restrict__ out)
{
    gemm_body(g_att, g_wh + (size_t)3 * K2DIM * N_DIM, bo, out);
}

// ---------------- fast exp ----------------
__device__ __forceinline__ float fast_exp(float x)
{
    float z  = x * 1.4426950408889634f;
    float fi = z + 12582912.0f;
    int   n  = __float_as_int(fi) - 0x4B400000;
    float f  = z - (fi - 12582912.0f);
    float p  = 1.3333558146e-3f;
    p = fmaf(p, f, 9.6181291918e-3f);
    p = fmaf(p, f, 5.5504108664e-2f);
    p = fmaf(p, f, 2.4022650695e-1f);
    p = fmaf(p, f, 6.9314718056e-1f);
    p = fmaf(p, f, 1.0f);
    return __int_as_float(__float_as_int(p) + (n << 23));
}

// ---------------- per-(b,s) head-mixing attention ----------------
// 64 threads/block; thread t handles heads t, t+64, t+128, t+192 of row m.
// 4 heads/thread quarters the broadcast LDS traffic per block (2 warps instead
// of 8 re-reading identical k/v words) -> kernel flips from L1- to FMA-bound.
// phase_shift is analytically dead (cos^2+sin^2=1; imaginary softmax discarded).
__global__ __launch_bounds__(64)
void attention_kernel()
{
    const int m = blockIdx.x;
    const int t = threadIdx.x;   // 0..63

    __shared__ float ks[N_DIM];
    __shared__ float vs[N_DIM];

    const float* qrow = g_q + (size_t)m * N_DIM;
    const float* krow = g_k + (size_t)m * N_DIM;
    const float* vrow = g_v + (size_t)m * N_DIM;

    // cooperative, coalesced load of k and v rows (8 float4 per thread)
    #pragma unroll
    for (int i = 0; i < 8; i++) {
        const int o4 = (i * 64 + t) * 4;
        *(float4*)&ks[o4] = *(const float4*)&krow[o4];
        *(float4*)&vs[o4] = *(const float4*)&vrow[o4];
    }

    const float scale = 0.35355339059327373f;   // 1/sqrt(8)
    ull q01[4], q23[4], q45[4], q67[4];
    #pragma unroll
    for (int hh = 0; hh < 4; hh++) {
        const int h = t + hh * 64;
        float4 a = *(const float4*)&qrow[h * 8];
        float4 b = *(const float4*)&qrow[h * 8 + 4];
        q01[hh] = pk2f(a.x * scale, a.y * scale);
        q23[hh] = pk2f(a.z * scale, a.w * scale);
        q45[hh] = pk2f(b.x * scale, b.y * scale);
        q67[hh] = pk2f(b.z * scale, b.w * scale);
    }

    __syncthreads();

    float sum[4] = {0.f, 0.f, 0.f, 0.f};
    ull o01[4] = {0, 0, 0, 0};
    ull o23[4] = {0, 0, 0, 0};
    ull o45[4] = {0, 0, 0, 0};
    ull o67[4] = {0, 0, 0, 0};

    #pragma unroll 2
    for (int g = 0; g < HEADS; g++) {
        const ulonglong2 ka = *(const ulonglong2*)&ks[g * 8];
        const ulonglong2 kb = *(const ulonglong2*)&ks[g * 8 + 4];
        const ulonglong2 va = *(const ulonglong2*)&vs[g * 8];
        const ulonglong2 vb = *(const ulonglong2*)&vs[g * 8 + 4];
        #pragma unroll
        for (int hh = 0; hh < 4; hh++) {
            ull s2;
            MULX2(s2, q01[hh], ka.x);
            FMAX2(s2, q23[hh], ka.y, s2);
            FMAX2(s2, q45[hh], kb.x, s2);
            FMAX2(s2, q67[hh], kb.y, s2);
            float sx, sy; UPKX2(sx, sy, s2);
            const float p = fast_exp(sx + sy);
            sum[hh] += p;
            const ull pp = pk2f(p, p);
            FMAX2(o01[hh], pp, va.x, o01[hh]);
            FMAX2(o23[hh], pp, va.y, o23[hh]);
            FMAX2(o45[hh], pp, vb.x, o45[hh]);
            FMAX2(o67[hh], pp, vb.y, o67[hh]);
        }
    }

    #pragma unroll
    for (int hh = 0; hh < 4; hh++) {
        const float inv = 1.0f / sum[hh];
        const ull iv = pk2f(inv, inv);
        MULX2(o01[hh], o01[hh], iv);
        MULX2(o23[hh], o23[hh], iv);
        MULX2(o45[hh], o45[hh], iv);
        MULX2(o67[hh], o67[hh], iv);
        float a, b;
        uint4 st;
        UPKX2(a, b, o01[hh]); st.x = pack2(a, b);
        UPKX2(a, b, o23[hh]); st.y = pack2(a, b);
        UPKX2(a, b, o45[hh]); st.z = pack2(a, b);
        UPKX2(a, b, o67[hh]); st.w = pack2(a, b);
        const int h = t + hh * 64;
        *(uint4*)&g_att[(size_t)m * N_DIM + h * 8] = st;
    }
}

// ---------------- launch ----------------
extern "C" void kernel_launch(void* const* d_in, const int* in_sizes, int n_in,
                              void* d_out, int out_size)
{
    const float* x  = (const float*)d_in[0];
    // d_in[1] = phase_shift: dead.
    const float* Wq = (const float*)d_in[2];
    const float* bq = (const float*)d_in[3];
    const float* Wk = (const float*)d_in[4];
    const float* bk = (const float*)d_in[5];
    const float* Wv = (const float*)d_in[6];
    const float* bv = (const float*)d_in[7];
    const float* Wo = (const float*)d_in[8];
    const float* bo = (const float*)d_in[9];
    float* out = (float*)d_out;

    cvt_all<<<dim3(2048, 5), 256>>>(x, Wq, Wk, Wv, Wo);
    qkv_gemm<<<dim3(N_DIM / 128, M_DIM / 128, 3), 256>>>(bq, bk, bv);
    attention_kernel<<<M_DIM, 64>>>();
    o_gemm<<<dim3(N_DIM / 128, M_DIM / 128, 1), 256>>>(bo, out);
}

// round 14
// speedup vs baseline: 2.1850x; 1.0076x over previous
#include <cuda_runtime.h>
#include <cuda_fp16.h>
#include <cstdint>

// Dims fixed: B=4, S=256, D_MODEL=2048, H=256, HEAD_DIM=8; M = B*S = 1024.
#define M_DIM 1024
#define N_DIM 2048
#define K_DIM 2048
#define HEADS 256
#define WSZ   ((size_t)K_DIM * N_DIM)

// ---------------- scratch ----------------
__device__ float  g_q  [M_DIM * N_DIM];
__device__ float  g_k  [M_DIM * N_DIM];
__device__ float  g_v  [M_DIM * N_DIM];
__device__ __half g_att[M_DIM * N_DIM];       // attention out, fp16 (k-contig)
__device__ __half g_xh [M_DIM * K_DIM];       // x as fp16 (k-contig)
__device__ __half g_whT[4 * WSZ];             // W^T as fp16: [z][n][k] (k-contig)

// ---------------- helpers ----------------
__device__ __forceinline__ uint32_t pack2(float lo, float hi) {
    __half2 h = __floats2half2_rn(lo, hi);
    return *(uint32_t*)&h;
}
__device__ __forceinline__ uint32_t smem_u32(const void* p) {
    uint32_t a;
    asm("{ .reg .u64 t; cvta.to.shared.u64 t, %1; cvt.u32.u64 %0, t; }" : "=r"(a) : "l"(p));
    return a;
}
#define CP_ASYNC16(dst, src) \
    asm volatile("cp.async.cg.shared.global [%0], [%1], 16;" :: "r"(dst), "l"(src))
#define CP_COMMIT() asm volatile("cp.async.commit_group;" ::: "memory")
#define CP_WAIT0()  asm volatile("cp.async.wait_group 0;"  ::: "memory")
#define CP_WAIT1()  asm volatile("cp.async.wait_group 1;"  ::: "memory")
#define CP_WAIT2()  asm volatile("cp.async.wait_group 2;"  ::: "memory")

#define LDSM4(r0, r1, r2, r3, addr)                                   \
    asm volatile("ldmatrix.sync.aligned.m8n8.x4.shared.b16 "          \
                 "{%0,%1,%2,%3}, [%4];"                                \
                 : "=r"(r0), "=r"(r1), "=r"(r2), "=r"(r3) : "r"(addr))

__device__ __forceinline__ void mma_f16(float* c,
                                        unsigned a0, unsigned a1, unsigned a2, unsigned a3,
                                        unsigned b0, unsigned b1)
{
    asm volatile(
        "mma.sync.aligned.m16n8k16.row.col.f32.f16.f16.f32 "
        "{%0,%1,%2,%3}, {%4,%5,%6,%7}, {%8,%9}, {%0,%1,%2,%3};\n"
        : "+f"(c[0]), "+f"(c[1]), "+f"(c[2]), "+f"(c[3])
        : "r"(a0), "r"(a1), "r"(a2), "r"(a3), "r"(b0), "r"(b1));
}

// f32x2 packed fp32 math (PTX sm_100+)
typedef unsigned long long ull;
__device__ __forceinline__ ull pk2f(float x, float y) {
    ull r; asm("mov.b64 %0, {%1, %2};" : "=l"(r) : "f"(x), "f"(y)); return r;
}
#define FMAX2(d, a, b, c) \
    asm("fma.rn.f32x2 %0, %1, %2, %3;" : "=l"(d) : "l"(a), "l"(b), "l"(c))
#define MULX2(d, a, b) \
    asm("mul.rn.f32x2 %0, %1, %2;" : "=l"(d) : "l"(a), "l"(b))
#define UPKX2(x, y, v) \
    asm("mov.b64 {%0, %1}, %2;" : "=f"(x), "=f"(y) : "l"(v))

// ---------------- prepass: x -> fp16; W -> fp16 transposed [n][k] ----------------
__global__ void cvt_all(const float* __restrict__ x,
                        const float* __restrict__ Wq, const float* __restrict__ Wk,
                        const float* __restrict__ Wv, const float* __restrict__ Wo)
{
    __shared__ float s[32][33];
    const int tx = threadIdx.x, ty = threadIdx.y;   // (32, 8)
    if (blockIdx.y < 4) {
        const float* W = (blockIdx.y == 0) ? Wq : (blockIdx.y == 1) ? Wk
                       : (blockIdx.y == 2) ? Wv : Wo;
        __half* D = g_whT + (size_t)blockIdx.y * WSZ;
        const int kb = (blockIdx.x & 63) * 32;       // 64 k-tiles
        const int nb = (blockIdx.x >> 6) * 32;       // 64 n-tiles
        #pragma unroll
        for (int j = 0; j < 32; j += 8)
            s[ty + j][tx] = W[(size_t)(kb + ty + j) * N_DIM + nb + tx];
        __syncthreads();
        #pragma unroll
        for (int j = 0; j < 32; j += 8)
            D[(size_t)(nb + ty + j) * K_DIM + kb + tx] = __float2half_rn(s[tx][ty + j]);
    } else if (blockIdx.x < 1024) {
        const int idx = blockIdx.x * 256 + ty * 32 + tx;
        const float* sp = x + (size_t)idx * 8;
        float4 a = *(const float4*)sp;
        float4 b = *(const float4*)(sp + 4);
        uint4 o;
        o.x = pack2(a.x, a.y); o.y = pack2(a.z, a.w);
        o.z = pack2(b.x, b.y); o.w = pack2(b.z, b.w);
        *(uint4*)&g_xh[(size_t)idx * 8] = o;
    }
}

// ---------------- fp16 GEMM: ldmatrix + 4-stage cp.async ----------------
// C[M,N] = A[M,K] @ W[K,N] + bias; A k-contig halves, BT = W^T k-contig halves.
// Block 128x128, BK=16, 256 thr, 8 warps 2x4, warp tile 64x32.
// Both smem tiles: 128 rows x 32B data + 16B pad (stride 48 -> LDSM phases
// conflict-free: banks 12i mod 32 distinct over any 8 consecutive rows).
#define NKCH  (K_DIM / 16)       // 128 chunks
#define TBUF  6144               // 128 * 48
#define STG_B (2 * TBUF)         // 12288 (A then B)
#define SMEMB (4 * STG_B)        // 49152

__device__ __forceinline__ void gemm_body(const __half* __restrict__ A,
                                          const __half* __restrict__ BT,
                                          const float* __restrict__ bias,
                                          float* __restrict__ C)
{
    extern __shared__ __align__(16) char sm[];
    const uint32_t sb = smem_u32(sm);

    const int tid  = threadIdx.x;
    const int lane = tid & 31;
    const int wid  = tid >> 5;
    const int wm   = wid >> 2;          // warp M base wm*64
    const int wn   = wid & 3;           // warp N base wn*32
    const int lr   = lane >> 2;
    const int lc   = lane & 3;
    const int bm   = blockIdx.y * 128;
    const int bn   = blockIdx.x * 128;

    // cp.async: each thread one 16B piece of A and one of B per chunk.
    const int rr = tid >> 1, hh = tid & 1;
    const __half* Asrc = A  + (size_t)(bm + rr) * K_DIM + hh * 8;
    const __half* Bsrc = BT + (size_t)(bn + rr) * K_DIM + hh * 8;
    const uint32_t aOff = (uint32_t)(rr * 48 + hh * 16);
    const uint32_t bOff = TBUF + aOff;

    // ldmatrix lane offsets
    const uint32_t laneA = (uint32_t)((lane & 15) * 48 + (lane >> 4) * 16);
    const uint32_t laneB = (uint32_t)(((lane & 7) + ((lane >> 4) << 3)) * 48
                                      + ((lane >> 3) & 1) * 16);

    float c[4][4][4];
    #pragma unroll
    for (int i = 0; i < 4; i++)
        #pragma unroll
        for (int j = 0; j < 4; j++)
            #pragma unroll
            for (int r = 0; r < 4; r++) c[i][j][r] = 0.0f;

    // prologue: chunks 0..2 into stages 0..2
    #pragma unroll
    for (int p = 0; p < 3; p++) {
        const uint32_t base = sb + p * STG_B;
        CP_ASYNC16(base + aOff, Asrc + (size_t)p * 16);
        CP_ASYNC16(base + bOff, Bsrc + (size_t)p * 16);
        CP_COMMIT();
    }

    for (int kt = 0; kt < NKCH; kt++) {
        const int s = kt & 3;
        if (kt < NKCH - 2)      { CP_WAIT2(); }
        else if (kt == NKCH - 2){ CP_WAIT1(); }
        else                    { CP_WAIT0(); }
        __syncthreads();

        if (kt + 3 < NKCH) {     // issue chunk kt+3 into stage (kt+3)&3 (freed)
            const uint32_t base = sb + ((kt + 3) & 3) * STG_B;
            CP_ASYNC16(base + aOff, Asrc + (size_t)(kt + 3) * 16);
            CP_ASYNC16(base + bOff, Bsrc + (size_t)(kt + 3) * 16);
            CP_COMMIT();
        }

        const uint32_t stg  = sb + s * STG_B;
        const uint32_t aAdr = stg + wm * 3072 + laneA;           // 64 rows * 48
        const uint32_t bAdr = stg + TBUF + wn * 1536 + laneB;    // 32 rows * 48

        unsigned af[4][4], bf[4][2];
        LDSM4(af[0][0], af[0][1], af[0][2], af[0][3], aAdr);
        LDSM4(af[1][0], af[1][1], af[1][2], af[1][3], aAdr + 768);
        LDSM4(af[2][0], af[2][1], af[2][2], af[2][3], aAdr + 1536);
        LDSM4(af[3][0], af[3][1], af[3][2], af[3][3], aAdr + 2304);
        LDSM4(bf[0][0], bf[0][1], bf[1][0], bf[1][1], bAdr);
        LDSM4(bf[2][0], bf[2][1], bf[3][0], bf[3][1], bAdr + 768);

        #pragma unroll
        for (int i = 0; i < 4; i++)
            #pragma unroll
            for (int j = 0; j < 4; j++)
                mma_f16(c[i][j], af[i][0], af[i][1], af[i][2], af[i][3],
                        bf[j][0], bf[j][1]);
    }

    // epilogue: bias + float2 stores (c0,c1 / c2,c3 adjacent columns)
    #pragma unroll
    for (int i = 0; i < 4; i++) {
        const int row0 = bm + wm * 64 + i * 16 + lr;
        #pragma unroll
        for (int j = 0; j < 4; j++) {
            const int col = bn + wn * 32 + j * 8 + 2 * lc;
            float2 bb = *(const float2*)(bias + col);
            float2 r0, r1;
            r0.x = c[i][j][0] + bb.x;  r0.y = c[i][j][1] + bb.y;
            r1.x = c[i][j][2] + bb.x;  r1.y = c[i][j][3] + bb.y;
            *(float2*)&C[(size_t)row0 * N_DIM + col]       = r0;
            *(float2*)&C[(size_t)(row0 + 8) * N_DIM + col] = r1;
        }
    }
}

__global__ __launch_bounds__(256, 2)
void qkv_gemm(const float* __restrict__ bq, const float* __restrict__ bk,
              const float* __restrict__ bv)
{
    const int z = blockIdx.z;
    const float* bias = (z == 0) ? bq : (z == 1) ? bk : bv;
    float* C = (z == 0) ? g_q : (z == 1) ? g_k : g_v;
    gemm_body(g_xh, g_whT + (size_t)z * WSZ, bias, C);
}

__global__ __launch_bounds__(256, 2)
void o_gemm(const float* __restrict__ bo, float* __restrict__ out)
{
    gemm_body(g_att, g_whT + (size_t)3 * WSZ, bo, out);
}

// ---------------- fast exp ----------------
__device__ __forceinline__ float fast_exp(float x)
{
    float z  = x * 1.4426950408889634f;
    float fi = z + 12582912.0f;
    int   n  = __float_as_int(fi) - 0x4B400000;
    float f  = z - (fi - 12582912.0f);
    float p  = 1.3333558146e-3f;
    p = fmaf(p, f, 9.6181291918e-3f);
    p = fmaf(p, f, 5.5504108664e-2f);
    p = fmaf(p, f, 2.4022650695e-1f);
    p = fmaf(p, f, 6.9314718056e-1f);
    p = fmaf(p, f, 1.0f);
    return __int_as_float(__float_as_int(p) + (n << 23));
}

// ---------------- per-(b,s) head-mixing attention ----------------
// 64 threads/block; thread t handles heads t, t+64, t+128, t+192 of row m.
// phase_shift is analytically dead (cos^2+sin^2=1; imaginary softmax discarded).
__global__ __launch_bounds__(64)
void attention_kernel()
{
    const int m = blockIdx.x;
    const int t = threadIdx.x;   // 0..63

    __shared__ float ks[N_DIM];
    __shared__ float vs[N_DIM];

    const float* qrow = g_q + (size_t)m * N_DIM;
    const float* krow = g_k + (size_t)m * N_DIM;
    const float* vrow = g_v + (size_t)m * N_DIM;

    #pragma unroll
    for (int i = 0; i < 8; i++) {
        const int o4 = (i * 64 + t) * 4;
        *(float4*)&ks[o4] = *(const float4*)&krow[o4];
        *(float4*)&vs[o4] = *(const float4*)&vrow[o4];
    }

    const float scale = 0.35355339059327373f;   // 1/sqrt(8)
    ull q01[4], q23[4], q45[4], q67[4];
    #pragma unroll
    for (int hh = 0; hh < 4; hh++) {
        const int h = t + hh * 64;
        float4 a = *(const float4*)&qrow[h * 8];
        float4 b = *(const float4*)&qrow[h * 8 + 4];
        q01[hh] = pk2f(a.x * scale, a.y * scale);
        q23[hh] = pk2f(a.z * scale, a.w * scale);
        q45[hh] = pk2f(b.x * scale, b.y * scale);
        q67[hh] = pk2f(b.z * scale, b.w * scale);
    }

    __syncthreads();

    float sum[4] = {0.f, 0.f, 0.f, 0.f};
    ull o01[4] = {0, 0, 0, 0};
    ull o23[4] = {0, 0, 0, 0};
    ull o45[4] = {0, 0, 0, 0};
    ull o67[4] = {0, 0, 0, 0};

    #pragma unroll 2
    for (int g = 0; g < HEADS; g++) {
        const ulonglong2 ka = *(const ulonglong2*)&ks[g * 8];
        const ulonglong2 kb = *(const ulonglong2*)&ks[g * 8 + 4];
        const ulonglong2 va = *(const ulonglong2*)&vs[g * 8];
        const ulonglong2 vb = *(const ulonglong2*)&vs[g * 8 + 4];
        #pragma unroll
        for (int hh = 0; hh < 4; hh++) {
            ull s2;
            MULX2(s2, q01[hh], ka.x);
            FMAX2(s2, q23[hh], ka.y, s2);
            FMAX2(s2, q45[hh], kb.x, s2);
            FMAX2(s2, q67[hh], kb.y, s2);
            float sx, sy; UPKX2(sx, sy, s2);
            const float p = fast_exp(sx + sy);
            sum[hh] += p;
            const ull pp = pk2f(p, p);
            FMAX2(o01[hh], pp, va.x, o01[hh]);
            FMAX2(o23[hh], pp, va.y, o23[hh]);
            FMAX2(o45[hh], pp, vb.x, o45[hh]);
            FMAX2(o67[hh], pp, vb.y, o67[hh]);
        }
    }

    #pragma unroll
    for (int hh = 0; hh < 4; hh++) {
        const float inv = 1.0f / sum[hh];
        const ull iv = pk2f(inv, inv);
        MULX2(o01[hh], o01[hh], iv);
        MULX2(o23[hh], o23[hh], iv);
        MULX2(o45[hh], o45[hh], iv);
        MULX2(o67[hh], o67[hh], iv);
        float a, b;
        uint4 st;
        UPKX2(a, b, o01[hh]); st.x = pack2(a, b);
        UPKX2(a, b, o23[hh]); st.y = pack2(a, b);
        UPKX2(a, b, o45[hh]); st.z = pack2(a, b);
        UPKX2(a, b, o67[hh]); st.w = pack2(a, b);
        const int h = t + hh * 64;
        *(uint4*)&g_att[(size_t)m * N_DIM + h * 8] = st;
    }
}

// ---------------- launch ----------------
extern "C" void kernel_launch(void* const* d_in, const int* in_sizes, int n_in,
                              void* d_out, int out_size)
{
    const float* x  = (const float*)d_in[0];
    // d_in[1] = phase_shift: dead.
    const float* Wq = (const float*)d_in[2];
    const float* bq = (const float*)d_in[3];
    const float* Wk = (const float*)d_in[4];
    const float* bk = (const float*)d_in[5];
    const float* Wv = (const float*)d_in[6];
    const float* bv = (const float*)d_in[7];
    const float* Wo = (const float*)d_in[8];
    const float* bo = (const float*)d_in[9];
    float* out = (float*)d_out;

    cudaFuncSetAttribute(qkv_gemm, cudaFuncAttributeMaxDynamicSharedMemorySize, SMEMB);
    cudaFuncSetAttribute(o_gemm,   cudaFuncAttributeMaxDynamicSharedMemorySize, SMEMB);

    cvt_all<<<dim3(4096, 5), dim3(32, 8)>>>(x, Wq, Wk, Wv, Wo);
    qkv_gemm<<<dim3(N_DIM / 128, M_DIM / 128, 3), 256, SMEMB>>>(bq, bk, bv);
    attention_kernel<<<M_DIM, 64>>>();
    o_gemm<<<dim3(N_DIM / 128, M_DIM / 128, 1), 256, SMEMB>>>(bo, out);
}

// round 15
// speedup vs baseline: 2.2606x; 1.0346x over previous
#include <cuda_runtime.h>
#include <cuda_fp16.h>
#include <cstdint>

// Dims fixed: B=4, S=256, D_MODEL=2048, H=256, HEAD_DIM=8; M = B*S = 1024.
#define M_DIM 1024
#define N_DIM 2048
#define K_DIM 2048
#define HEADS 256
#define WSZ   ((size_t)K_DIM * N_DIM)

// ---------------- scratch ----------------
__device__ float  g_q  [M_DIM * N_DIM];       // q; later: o-partial 0
__device__ float  g_k  [M_DIM * N_DIM];       // k; later: o-partial 1
__device__ float  g_v  [M_DIM * N_DIM];
__device__ __half g_att[M_DIM * N_DIM];       // attention out, fp16 (k-contig)
__device__ __half g_xh [M_DIM * K_DIM];       // x as fp16 (k-contig)
__device__ __half g_whT[4 * WSZ];             // W^T as fp16: [z][n][k] (k-contig)
__device__ float  g_zero[N_DIM];              // zero bias (zero-initialized)

// ---------------- helpers ----------------
__device__ __forceinline__ uint32_t pack2(float lo, float hi) {
    __half2 h = __floats2half2_rn(lo, hi);
    return *(uint32_t*)&h;
}
__device__ __forceinline__ uint32_t smem_u32(const void* p) {
    uint32_t a;
    asm("{ .reg .u64 t; cvta.to.shared.u64 t, %1; cvt.u32.u64 %0, t; }" : "=r"(a) : "l"(p));
    return a;
}
#define CP_ASYNC16(dst, src) \
    asm volatile("cp.async.cg.shared.global [%0], [%1], 16;" :: "r"(dst), "l"(src))
#define CP_COMMIT() asm volatile("cp.async.commit_group;" ::: "memory")
#define CP_WAIT0()  asm volatile("cp.async.wait_group 0;"  ::: "memory")
#define CP_WAIT1()  asm volatile("cp.async.wait_group 1;"  ::: "memory")
#define CP_WAIT2()  asm volatile("cp.async.wait_group 2;"  ::: "memory")

#define LDSM4(r0, r1, r2, r3, addr)                                   \
    asm volatile("ldmatrix.sync.aligned.m8n8.x4.shared.b16 "          \
                 "{%0,%1,%2,%3}, [%4];"                                \
                 : "=r"(r0), "=r"(r1), "=r"(r2), "=r"(r3) : "r"(addr))

__device__ __forceinline__ void mma_f16(float* c,
                                        unsigned a0, unsigned a1, unsigned a2, unsigned a3,
                                        unsigned b0, unsigned b1)
{
    asm volatile(
        "mma.sync.aligned.m16n8k16.row.col.f32.f16.f16.f32 "
        "{%0,%1,%2,%3}, {%4,%5,%6,%7}, {%8,%9}, {%0,%1,%2,%3};\n"
        : "+f"(c[0]), "+f"(c[1]), "+f"(c[2]), "+f"(c[3])
        : "r"(a0), "r"(a1), "r"(a2), "r"(a3), "r"(b0), "r"(b1));
}

// f32x2 packed fp32 math (PTX sm_100+)
typedef unsigned long long ull;
__device__ __forceinline__ ull pk2f(float x, float y) {
    ull r; asm("mov.b64 %0, {%1, %2};" : "=l"(r) : "f"(x), "f"(y)); return r;
}
#define FMAX2(d, a, b, c) \
    asm("fma.rn.f32x2 %0, %1, %2, %3;" : "=l"(d) : "l"(a), "l"(b), "l"(c))
#define MULX2(d, a, b) \
    asm("mul.rn.f32x2 %0, %1, %2;" : "=l"(d) : "l"(a), "l"(b))
#define UPKX2(x, y, v) \
    asm("mov.b64 {%0, %1}, %2;" : "=f"(x), "=f"(y) : "l"(v))

// ---------------- prepass: x -> fp16; W -> fp16 transposed [n][k] ----------------
// 64x64 f32 tiles; transposed writes are uint4 (8 halves along k) -> coalesced.
__global__ void cvt_all(const float* __restrict__ x,
                        const float* __restrict__ Wq, const float* __restrict__ Wk,
                        const float* __restrict__ Wv, const float* __restrict__ Wo)
{
    __shared__ float s[64][65];
    const int tx = threadIdx.x, ty = threadIdx.y;   // (32, 8)
    const int tid = ty * 32 + tx;
    if (blockIdx.y < 4) {
        const float* W = (blockIdx.y == 0) ? Wq : (blockIdx.y == 1) ? Wk
                       : (blockIdx.y == 2) ? Wv : Wo;
        __half* D = g_whT + (size_t)blockIdx.y * WSZ;
        const int kb = (blockIdx.x & 31) * 64;
        const int nb = (blockIdx.x >> 5) * 64;
        #pragma unroll
        for (int j = 0; j < 8; j++) {
            const int r = ty + j * 8;
            const float* src = W + (size_t)(kb + r) * N_DIM + nb;
            s[r][tx]      = src[tx];
            s[r][tx + 32] = src[tx + 32];
        }
        __syncthreads();
        #pragma unroll
        for (int i = 0; i < 2; i++) {
            const int u  = tid * 2 + i;
            const int n  = u >> 3;
            const int ch = (u & 7) * 8;
            uint4 o;
            o.x = pack2(s[ch + 0][n], s[ch + 1][n]);
            o.y = pack2(s[ch + 2][n], s[ch + 3][n]);
            o.z = pack2(s[ch + 4][n], s[ch + 5][n]);
            o.w = pack2(s[ch + 6][n], s[ch + 7][n]);
            *(uint4*)&D[(size_t)(nb + n) * K_DIM + kb + ch] = o;
        }
    } else if (blockIdx.x < 1024) {
        const int idx = blockIdx.x * 256 + tid;
        const float* sp = x + (size_t)idx * 8;
        float4 a = *(const float4*)sp;
        float4 b = *(const float4*)(sp + 4);
        uint4 o;
        o.x = pack2(a.x, a.y); o.y = pack2(a.z, a.w);
        o.z = pack2(b.x, b.y); o.w = pack2(b.z, b.w);
        *(uint4*)&g_xh[(size_t)idx * 8] = o;
    }
}

// ---------------- fp16 GEMM: ldmatrix + 4-stage cp.async ----------------
// C[M,N] = A[M,K'] @ W' + bias over numCh k16-chunks; A,BT k-contig fp16.
// Block 128x128, 256 thr, 8 warps 2x4, warp tile 64x32. Tile rows: 32B data
// + 16B pad (stride 48 -> LDSM phases conflict-free).
#define TBUF  6144               // 128 * 48
#define STG_B (2 * TBUF)         // 12288 (A then B)
#define SMEMB (4 * STG_B)        // 49152

__device__ __forceinline__ void gemm_body(const __half* __restrict__ A,
                                          const __half* __restrict__ BT,
                                          const float* __restrict__ bias,
                                          float* __restrict__ C, int numCh)
{
    extern __shared__ __align__(16) char sm[];
    const uint32_t sb = smem_u32(sm);

    const int tid  = threadIdx.x;
    const int lane = tid & 31;
    const int wid  = tid >> 5;
    const int wm   = wid >> 2;
    const int wn   = wid & 3;
    const int lr   = lane >> 2;
    const int lc   = lane & 3;
    const int bm   = blockIdx.y * 128;
    const int bn   = blockIdx.x * 128;

    const int rr = tid >> 1, hh = tid & 1;
    const __half* Asrc = A  + (size_t)(bm + rr) * K_DIM + hh * 8;
    const __half* Bsrc = BT + (size_t)(bn + rr) * K_DIM + hh * 8;
    const uint32_t aOff = (uint32_t)(rr * 48 + hh * 16);
    const uint32_t bOff = TBUF + aOff;

    const uint32_t laneA = (uint32_t)((lane & 15) * 48 + (lane >> 4) * 16);
    const uint32_t laneB = (uint32_t)(((lane & 7) + ((lane >> 4) << 3)) * 48
                                      + ((lane >> 3) & 1) * 16);

    float c[4][4][4];
    #pragma unroll
    for (int i = 0; i < 4; i++)
        #pragma unroll
        for (int j = 0; j < 4; j++)
            #pragma unroll
            for (int r = 0; r < 4; r++) c[i][j][r] = 0.0f;

    #pragma unroll
    for (int p = 0; p < 3; p++) {
        const uint32_t base = sb + p * STG_B;
        CP_ASYNC16(base + aOff, Asrc + (size_t)p * 16);
        CP_ASYNC16(base + bOff, Bsrc + (size_t)p * 16);
        CP_COMMIT();
    }

    for (int kt = 0; kt < numCh; kt++) {
        const int s = kt & 3;
        if (kt < numCh - 2)       { CP_WAIT2(); }
        else if (kt == numCh - 2) { CP_WAIT1(); }
        else                      { CP_WAIT0(); }
        __syncthreads();

        if (kt + 3 < numCh) {
            const uint32_t base = sb + ((kt + 3) & 3) * STG_B;
            CP_ASYNC16(base + aOff, Asrc + (size_t)(kt + 3) * 16);
            CP_ASYNC16(base + bOff, Bsrc + (size_t)(kt + 3) * 16);
            CP_COMMIT();
        }

        const uint32_t stg  = sb + s * STG_B;
        const uint32_t aAdr = stg + wm * 3072 + laneA;
        const uint32_t bAdr = stg + TBUF + wn * 1536 + laneB;

        unsigned af[4][4], bf[4][2];
        LDSM4(af[0][0], af[0][1], af[0][2], af[0][3], aAdr);
        LDSM4(af[1][0], af[1][1], af[1][2], af[1][3], aAdr + 768);
        LDSM4(af[2][0], af[2][1], af[2][2], af[2][3], aAdr + 1536);
        LDSM4(af[3][0], af[3][1], af[3][2], af[3][3], aAdr + 2304);
        LDSM4(bf[0][0], bf[0][1], bf[1][0], bf[1][1], bAdr);
        LDSM4(bf[2][0], bf[2][1], bf[3][0], bf[3][1], bAdr + 768);

        #pragma unroll
        for (int i = 0; i < 4; i++)
            #pragma unroll
            for (int j = 0; j < 4; j++)
                mma_f16(c[i][j], af[i][0], af[i][1], af[i][2], af[i][3],
                        bf[j][0], bf[j][1]);
    }

    #pragma unroll
    for (int i = 0; i < 4; i++) {
        const int row0 = bm + wm * 64 + i * 16 + lr;
        #pragma unroll
        for (int j = 0; j < 4; j++) {
            const int col = bn + wn * 32 + j * 8 + 2 * lc;
            float2 bb = *(const float2*)(bias + col);
            float2 r0, r1;
            r0.x = c[i][j][0] + bb.x;  r0.y = c[i][j][1] + bb.y;
            r1.x = c[i][j][2] + bb.x;  r1.y = c[i][j][3] + bb.y;
            *(float2*)&C[(size_t)row0 * N_DIM + col]       = r0;
            *(float2*)&C[(size_t)(row0 + 8) * N_DIM + col] = r1;
        }
    }
}

__global__ __launch_bounds__(256, 2)
void qkv_gemm(const float* __restrict__ bq, const float* __restrict__ bk,
              const float* __restrict__ bv)
{
    const int z = blockIdx.z;
    const float* bias = (z == 0) ? bq : (z == 1) ? bk : bv;
    float* C = (z == 0) ? g_q : (z == 1) ? g_k : g_v;
    gemm_body(g_xh, g_whT + (size_t)z * WSZ, bias, C, 128);
}

// Split-K=2: z=0 computes K[0,1024) + bias -> g_q; z=1 computes K[1024,2048)
// + zero-bias -> g_k. Deterministic: reduce adds exactly two partials in
// fixed order. (g_q/g_k are dead after attention_kernel.)
__global__ __launch_bounds__(256, 2)
void o_gemm(const float* __restrict__ bo)
{
    const int z = blockIdx.z;
    const __half* A  = g_att + (size_t)z * 1024;
    const __half* BT = g_whT + (size_t)3 * WSZ + (size_t)z * 1024;
    gemm_body(A, BT, z == 0 ? bo : g_zero, z == 0 ? g_q : g_k, 64);
}

__global__ __launch_bounds__(256)
void reduce_o(float* __restrict__ out)
{
    const int i = (blockIdx.x * 256 + threadIdx.x) * 4;
    float4 a = *(const float4*)&g_q[i];
    float4 b = *(const float4*)&g_k[i];
    a.x += b.x; a.y += b.y; a.z += b.z; a.w += b.w;
    *(float4*)&out[i] = a;
}

// ---------------- fast exp ----------------
__device__ __forceinline__ float fast_exp(float x)
{
    float z  = x * 1.4426950408889634f;
    float fi = z + 12582912.0f;
    int   n  = __float_as_int(fi) - 0x4B400000;
    float f  = z - (fi - 12582912.0f);
    float p  = 1.3333558146e-3f;
    p = fmaf(p, f, 9.6181291918e-3f);
    p = fmaf(p, f, 5.5504108664e-2f);
    p = fmaf(p, f, 2.4022650695e-1f);
    p = fmaf(p, f, 6.9314718056e-1f);
    p = fmaf(p, f, 1.0f);
    return __int_as_float(__float_as_int(p) + (n << 23));
}

// ---------------- per-(b,s) head-mixing attention ----------------
// 64 threads/block; thread t handles heads t, t+64, t+128, t+192 of row m.
// phase_shift is analytically dead (cos^2+sin^2=1; imaginary softmax discarded).
__global__ __launch_bounds__(64)
void attention_kernel()
{
    const int m = blockIdx.x;
    const int t = threadIdx.x;   // 0..63

    __shared__ float ks[N_DIM];
    __shared__ float vs[N_DIM];

    const float* qrow = g_q + (size_t)m * N_DIM;
    const float* krow = g_k + (size_t)m * N_DIM;
    const float* vrow = g_v + (size_t)m * N_DIM;

    #pragma unroll
    for (int i = 0; i < 8; i++) {
        const int o4 = (i * 64 + t) * 4;
        *(float4*)&ks[o4] = *(const float4*)&krow[o4];
        *(float4*)&vs[o4] = *(const float4*)&vrow[o4];
    }

    const float scale = 0.35355339059327373f;   // 1/sqrt(8)
    ull q01[4], q23[4], q45[4], q67[4];
    #pragma unroll
    for (int hh = 0; hh < 4; hh++) {
        const int h = t + hh * 64;
        float4 a = *(const float4*)&qrow[h * 8];
        float4 b = *(const float4*)&qrow[h * 8 + 4];
        q01[hh] = pk2f(a.x * scale, a.y * scale);
        q23[hh] = pk2f(a.z * scale, a.w * scale);
        q45[hh] = pk2f(b.x * scale, b.y * scale);
        q67[hh] = pk2f(b.z * scale, b.w * scale);
    }

    __syncthreads();

    float sum[4] = {0.f, 0.f, 0.f, 0.f};
    ull o01[4] = {0, 0, 0, 0};
    ull o23[4] = {0, 0, 0, 0};
    ull o45[4] = {0, 0, 0, 0};
    ull o67[4] = {0, 0, 0, 0};

    #pragma unroll 2
    for (int g = 0; g < HEADS; g++) {
        const ulonglong2 ka = *(const ulonglong2*)&ks[g * 8];
        const ulonglong2 kb = *(const ulonglong2*)&ks[g * 8 + 4];
        const ulonglong2 va = *(const ulonglong2*)&vs[g * 8];
        const ulonglong2 vb = *(const ulonglong2*)&vs[g * 8 + 4];
        #pragma unroll
        for (int hh = 0; hh < 4; hh++) {
            ull s2;
            MULX2(s2, q01[hh], ka.x);
            FMAX2(s2, q23[hh], ka.y, s2);
            FMAX2(s2, q45[hh], kb.x, s2);
            FMAX2(s2, q67[hh], kb.y, s2);
            float sx, sy; UPKX2(sx, sy, s2);
            const float p = fast_exp(sx + sy);
            sum[hh] += p;
            const ull pp = pk2f(p, p);
            FMAX2(o01[hh], pp, va.x, o01[hh]);
            FMAX2(o23[hh], pp, va.y, o23[hh]);
            FMAX2(o45[hh], pp, vb.x, o45[hh]);
            FMAX2(o67[hh], pp, vb.y, o67[hh]);
        }
    }

    #pragma unroll
    for (int hh = 0; hh < 4; hh++) {
        const float inv = 1.0f / sum[hh];
        const ull iv = pk2f(inv, inv);
        MULX2(o01[hh], o01[hh], iv);
        MULX2(o23[hh], o23[hh], iv);
        MULX2(o45[hh], o45[hh], iv);
        MULX2(o67[hh], o67[hh], iv);
        float a, b;
        uint4 st;
        UPKX2(a, b, o01[hh]); st.x = pack2(a, b);
        UPKX2(a, b, o23[hh]); st.y = pack2(a, b);
        UPKX2(a, b, o45[hh]); st.z = pack2(a, b);
        UPKX2(a, b, o67[hh]); st.w = pack2(a, b);
        const int h = t + hh * 64;
        *(uint4*)&g_att[(size_t)m * N_DIM + h * 8] = st;
    }
}

// ---------------- launch ----------------
extern "C" void kernel_launch(void* const* d_in, const int* in_sizes, int n_in,
                              void* d_out, int out_size)
{
    const float* x  = (const float*)d_in[0];
    // d_in[1] = phase_shift: dead.
    const float* Wq = (const float*)d_in[2];
    const float* bq = (const float*)d_in[3];
    const float* Wk = (const float*)d_in[4];
    const float* bk = (const float*)d_in[5];
    const float* Wv = (const float*)d_in[6];
    const float* bv = (const float*)d_in[7];
    const float* Wo = (const float*)d_in[8];
    const float* bo = (const float*)d_in[9];
    float* out = (float*)d_out;

    cudaFuncSetAttribute(qkv_gemm, cudaFuncAttributeMaxDynamicSharedMemorySize, SMEMB);
    cudaFuncSetAttribute(o_gemm,   cudaFuncAttributeMaxDynamicSharedMemorySize, SMEMB);

    cvt_all<<<dim3(1024, 5), dim3(32, 8)>>>(x, Wq, Wk, Wv, Wo);
    qkv_gemm<<<dim3(N_DIM / 128, M_DIM / 128, 3), 256, SMEMB>>>(bq, bk, bv);
    attention_kernel<<<M_DIM, 64>>>();
    o_gemm<<<dim3(N_DIM / 128, M_DIM / 128, 2), 256, SMEMB>>>(bo);
    reduce_o<<<2048, 256>>>(out);
}